// round 1
// baseline (speedup 1.0000x reference)
#include <cuda_runtime.h>
#include <cuda_bf16.h>
#include <math.h>

#define SEQ     2048
#define HIDDEN  1024
#define NH      16
#define HD      64
#define NL      8
#define VOCABSZ 50272
#define FFN     4096
#define EPSV    1e-5f

// ---------------- scratch (device globals; no allocs allowed) ----------------
__device__ float g_x  [(size_t)SEQ * HIDDEN];          // residual stream
__device__ float g_h  [(size_t)SEQ * HIDDEN];          // normed activations
__device__ float g_qkv[(size_t)SEQ * 3 * HIDDEN];      // qkv projections
__device__ float g_att[(size_t)SEQ * HIDDEN];          // attention context
__device__ float g_mid[(size_t)SEQ * FFN];             // ffn intermediate
__device__ float g_scores[(size_t)NH * SEQ * SEQ];     // attention probs

// ---------------- reduction helpers ----------------
__device__ __forceinline__ float warpSum(float v) {
    #pragma unroll
    for (int o = 16; o; o >>= 1) v += __shfl_xor_sync(0xffffffffu, v, o);
    return v;
}
__device__ __forceinline__ float warpMax(float v) {
    #pragma unroll
    for (int o = 16; o; o >>= 1) v = fmaxf(v, __shfl_xor_sync(0xffffffffu, v, o));
    return v;
}
__device__ __forceinline__ float blockReduceSum(float v, float* red) {
    int lane = threadIdx.x & 31, w = threadIdx.x >> 5;
    v = warpSum(v);
    if (lane == 0) red[w] = v;
    __syncthreads();
    if (w == 0) {
        float r = (lane < (int)(blockDim.x >> 5)) ? red[lane] : 0.0f;
        r = warpSum(r);
        if (lane == 0) red[0] = r;
    }
    __syncthreads();
    float out = red[0];
    __syncthreads();
    return out;
}
__device__ __forceinline__ float blockReduceMax(float v, float* red) {
    int lane = threadIdx.x & 31, w = threadIdx.x >> 5;
    v = warpMax(v);
    if (lane == 0) red[w] = v;
    __syncthreads();
    if (w == 0) {
        float r = (lane < (int)(blockDim.x >> 5)) ? red[lane] : -INFINITY;
        r = warpMax(r);
        if (lane == 0) red[0] = r;
    }
    __syncthreads();
    float out = red[0];
    __syncthreads();
    return out;
}

// ---------------- embedding + rmsnorm ----------------
__global__ void embed_rmsnorm_kernel(const int* __restrict__ ids,
                                     const float* __restrict__ wte,
                                     float* __restrict__ out) {
    __shared__ float red[32];
    int t = blockIdx.x;
    const float* row = wte + (size_t)ids[t] * HIDDEN;
    float v[4]; float ss = 0.0f;
    #pragma unroll
    for (int i = 0; i < 4; i++) {
        v[i] = row[threadIdx.x + i * 256];
        ss += v[i] * v[i];
    }
    ss = blockReduceSum(ss, red);
    float sc = rsqrtf(ss * (1.0f / HIDDEN) + EPSV);
    #pragma unroll
    for (int i = 0; i < 4; i++)
        out[(size_t)t * HIDDEN + threadIdx.x + i * 256] = v[i] * sc;
}

// ---------------- rmsnorm over rows of HIDDEN ----------------
__global__ void rmsnorm_kernel(const float* __restrict__ in, float* __restrict__ out) {
    __shared__ float red[32];
    int t = blockIdx.x;
    const float* row = in + (size_t)t * HIDDEN;
    float v[4]; float ss = 0.0f;
    #pragma unroll
    for (int i = 0; i < 4; i++) {
        v[i] = row[threadIdx.x + i * 256];
        ss += v[i] * v[i];
    }
    ss = blockReduceSum(ss, red);
    float sc = rsqrtf(ss * (1.0f / HIDDEN) + EPSV);
    #pragma unroll
    for (int i = 0; i < 4; i++)
        out[(size_t)t * HIDDEN + threadIdx.x + i * 256] = v[i] * sc;
}

// ---------------- per-head rmsnorm + rope on q,k ----------------
// grid (SEQ, NH, 2), 32 threads. thread i owns elements (2i, 2i+1) = rope pair i.
__global__ void qknorm_rope_kernel(float* __restrict__ qkv) {
    int t = blockIdx.x, h = blockIdx.y, w = blockIdx.z;
    float* p = qkv + (size_t)t * (3 * HIDDEN) + (size_t)w * HIDDEN + h * HD;
    int i = threadIdx.x;
    float x0 = p[2 * i], x1 = p[2 * i + 1];
    float ss = warpSum(x0 * x0 + x1 * x1);
    float sc = rsqrtf(ss * (1.0f / HD) + EPSV);
    x0 *= sc; x1 *= sc;
    // match jax fp32 rounding: inv_freq rounded to fp32, angle = fp32(t)*inv_freq
    float invf = (float)pow(10000.0, -(double)(2 * i) / (double)HD);
    float ang = (float)t * invf;
    float s, c;
    sincosf(ang, &s, &c);
    // out[2i] = x_odd*c - x_even*s ; out[2i+1] = x_odd*s + x_even*c
    p[2 * i]     = x1 * c - x0 * s;
    p[2 * i + 1] = x1 * s + x0 * c;
}

// ---------------- attention: scores + softmax (causal) ----------------
// grid (SEQ, NH), 256 threads. Stores probabilities into g_scores.
__global__ void attn_scores_kernel(const float* __restrict__ qkv,
                                   float* __restrict__ scores) {
    __shared__ float q[HD];
    __shared__ float red[32];
    int i = blockIdx.x, h = blockIdx.y;
    int tid = threadIdx.x;
    int nk = i + 1;
    if (tid < HD) q[tid] = qkv[(size_t)i * (3 * HIDDEN) + h * HD + tid];
    __syncthreads();

    float sv[8];
    float lmax = -INFINITY;
    int cnt = 0;
    for (int j = tid; j < nk; j += 256) {
        const float4* k4 = (const float4*)(qkv + (size_t)j * (3 * HIDDEN) + HIDDEN + h * HD);
        float d = 0.0f;
        #pragma unroll
        for (int c4 = 0; c4 < HD / 4; c4++) {
            float4 kv = k4[c4];
            d += q[4 * c4 + 0] * kv.x + q[4 * c4 + 1] * kv.y
               + q[4 * c4 + 2] * kv.z + q[4 * c4 + 3] * kv.w;
        }
        d *= 0.125f;  // 1/sqrt(64)
        sv[cnt++] = d;
        lmax = fmaxf(lmax, d);
    }
    float m = blockReduceMax(lmax, red);
    float lsum = 0.0f;
    for (int c = 0; c < cnt; c++) { sv[c] = expf(sv[c] - m); lsum += sv[c]; }
    float s = blockReduceSum(lsum, red);
    float rinv = 1.0f / s;
    cnt = 0;
    for (int j = tid; j < nk; j += 256)
        scores[((size_t)h * SEQ + i) * SEQ + j] = sv[cnt++] * rinv;
}

// ---------------- attention: O = P @ V ----------------
// grid (SEQ, NH), 256 threads = 4 j-partitions x 64 dims.
__global__ void attn_av_kernel(const float* __restrict__ qkv,
                               const float* __restrict__ scores,
                               float* __restrict__ out) {
    __shared__ float sa[4][HD];
    int i = blockIdx.x, h = blockIdx.y;
    int tid = threadIdx.x;
    int d = tid & 63, part = tid >> 6;
    const float* pr = scores + ((size_t)h * SEQ + i) * SEQ;
    const float* vb = qkv + 2 * HIDDEN + h * HD + d;
    float acc = 0.0f;
    for (int j = part; j <= i; j += 4)
        acc += pr[j] * vb[(size_t)j * (3 * HIDDEN)];
    sa[part][d] = acc;
    __syncthreads();
    if (part == 0)
        out[(size_t)i * HIDDEN + h * HD + d] = sa[0][d] + sa[1][d] + sa[2][d] + sa[3][d];
}

// ---------------- tiled SGEMM: C[M,N] = A[M,K] @ B[N,K]^T ----------------
// EPI 0: C = AB^T     EPI 1: C = R + AB^T     EPI 2: C = relu(AB^T)^2
// BM=BN=64, BK=16, 256 threads, 4x4 register tile. M%64==0, K%16==0; N guarded.
template <int EPI>
__global__ void gemm64_kernel(const float* __restrict__ A, const float* __restrict__ B,
                              float* __restrict__ C, const float* __restrict__ R,
                              int M, int N, int K) {
    __shared__ float As[16][68];
    __shared__ float Bs[16][68];
    int bm = blockIdx.y * 64, bn = blockIdx.x * 64;
    int tid = threadIdx.x;
    int lr = tid >> 2, lk = (tid & 3) * 4;   // loader: row, k-offset
    int tm = (tid >> 4) * 4, tn = (tid & 15) * 4;
    float c[4][4] = {};

    for (int k0 = 0; k0 < K; k0 += 16) {
        float4 av = *(const float4*)(A + (size_t)(bm + lr) * K + k0 + lk);
        As[lk + 0][lr] = av.x; As[lk + 1][lr] = av.y;
        As[lk + 2][lr] = av.z; As[lk + 3][lr] = av.w;
        float4 bv = make_float4(0.f, 0.f, 0.f, 0.f);
        if (bn + lr < N) bv = *(const float4*)(B + (size_t)(bn + lr) * K + k0 + lk);
        Bs[lk + 0][lr] = bv.x; Bs[lk + 1][lr] = bv.y;
        Bs[lk + 2][lr] = bv.z; Bs[lk + 3][lr] = bv.w;
        __syncthreads();
        #pragma unroll
        for (int kk = 0; kk < 16; kk++) {
            float a0 = As[kk][tm + 0], a1 = As[kk][tm + 1],
                  a2 = As[kk][tm + 2], a3 = As[kk][tm + 3];
            float b0 = Bs[kk][tn + 0], b1 = Bs[kk][tn + 1],
                  b2 = Bs[kk][tn + 2], b3 = Bs[kk][tn + 3];
            c[0][0] += a0 * b0; c[0][1] += a0 * b1; c[0][2] += a0 * b2; c[0][3] += a0 * b3;
            c[1][0] += a1 * b0; c[1][1] += a1 * b1; c[1][2] += a1 * b2; c[1][3] += a1 * b3;
            c[2][0] += a2 * b0; c[2][1] += a2 * b1; c[2][2] += a2 * b2; c[2][3] += a2 * b3;
            c[3][0] += a3 * b0; c[3][1] += a3 * b1; c[3][2] += a3 * b2; c[3][3] += a3 * b3;
        }
        __syncthreads();
    }

    #pragma unroll
    for (int i = 0; i < 4; i++) {
        int m = bm + tm + i;
        #pragma unroll
        for (int j = 0; j < 4; j++) {
            int n = bn + tn + j;
            if (n < N) {
                float v = c[i][j];
                if (EPI == 1) v += R[(size_t)m * N + n];
                if (EPI == 2) { v = fmaxf(v, 0.0f); v = v * v; }
                C[(size_t)m * N + n] = v;
            }
        }
    }
}

// ---------------- host launcher ----------------
extern "C" void kernel_launch(void* const* d_in, const int* in_sizes, int n_in,
                              void* d_out, int out_size) {
    const int*   ids  = (const int*)d_in[0];
    const float* wte  = (const float*)d_in[1];
    const float* wqkv = (const float*)d_in[2];
    const float* wo   = (const float*)d_in[3];
    const float* w1   = (const float*)d_in[4];
    const float* w2   = (const float*)d_in[5];
    const float* lm   = (const float*)d_in[6];
    float* out = (float*)d_out;

    float *px, *ph, *pqkv, *patt, *pmid, *pscr;
    cudaGetSymbolAddress((void**)&px,   g_x);
    cudaGetSymbolAddress((void**)&ph,   g_h);
    cudaGetSymbolAddress((void**)&pqkv, g_qkv);
    cudaGetSymbolAddress((void**)&patt, g_att);
    cudaGetSymbolAddress((void**)&pmid, g_mid);
    cudaGetSymbolAddress((void**)&pscr, g_scores);

    embed_rmsnorm_kernel<<<SEQ, 256>>>(ids, wte, px);

    for (int l = 0; l < NL; l++) {
        const float* wqkv_l = wqkv + (size_t)l * 3 * HIDDEN * HIDDEN;
        const float* wo_l   = wo   + (size_t)l * HIDDEN * HIDDEN;
        const float* w1_l   = w1   + (size_t)l * FFN * HIDDEN;
        const float* w2_l   = w2   + (size_t)l * HIDDEN * FFN;

        rmsnorm_kernel<<<SEQ, 256>>>(px, ph);
        gemm64_kernel<0><<<dim3((3 * HIDDEN) / 64, SEQ / 64), 256>>>(
            ph, wqkv_l, pqkv, nullptr, SEQ, 3 * HIDDEN, HIDDEN);
        qknorm_rope_kernel<<<dim3(SEQ, NH, 2), 32>>>(pqkv);
        attn_scores_kernel<<<dim3(SEQ, NH), 256>>>(pqkv, pscr);
        attn_av_kernel<<<dim3(SEQ, NH), 256>>>(pqkv, pscr, patt);
        gemm64_kernel<1><<<dim3(HIDDEN / 64, SEQ / 64), 256>>>(
            patt, wo_l, px, px, SEQ, HIDDEN, HIDDEN);

        rmsnorm_kernel<<<SEQ, 256>>>(px, ph);
        gemm64_kernel<2><<<dim3(FFN / 64, SEQ / 64), 256>>>(
            ph, w1_l, pmid, nullptr, SEQ, FFN, HIDDEN);
        gemm64_kernel<1><<<dim3(HIDDEN / 64, SEQ / 64), 256>>>(
            pmid, w2_l, px, px, SEQ, HIDDEN, FFN);
    }

    rmsnorm_kernel<<<SEQ, 256>>>(px, ph);
    gemm64_kernel<0><<<dim3((VOCABSZ + 63) / 64, SEQ / 64), 256>>>(
        ph, lm, out, nullptr, SEQ, VOCABSZ, HIDDEN);
}

// round 3
// speedup vs baseline: 2.3156x; 2.3156x over previous
#include <cuda_runtime.h>
#include <cuda_bf16.h>
#include <math.h>
#include <stdint.h>

#define SEQ     2048
#define HIDDEN  1024
#define NH      16
#define HD      64
#define NL      8
#define VOCABSZ 50272
#define FFN     4096
#define EPSV    1e-5f

// ---------------- scratch (device globals; no allocs allowed) ----------------
__device__ float g_x  [(size_t)SEQ * HIDDEN];
__device__ float g_h  [(size_t)SEQ * HIDDEN];
__device__ float g_qkv[(size_t)SEQ * 3 * HIDDEN];
__device__ float g_att[(size_t)SEQ * HIDDEN];
__device__ float g_mid[(size_t)SEQ * FFN];
__device__ float g_scores[(size_t)NH * SEQ * SEQ];
__device__ float g_cos[(size_t)SEQ * (HD / 2)];
__device__ float g_sin[(size_t)SEQ * (HD / 2)];

// ---------------- helpers ----------------
__device__ __forceinline__ uint32_t smem_u32(const void* p) {
    uint32_t a;
    asm("{ .reg .u64 t; cvta.to.shared.u64 t, %1; cvt.u32.u64 %0, t; }" : "=r"(a) : "l"(p));
    return a;
}
__device__ __forceinline__ float warpSum(float v) {
    #pragma unroll
    for (int o = 16; o; o >>= 1) v += __shfl_xor_sync(0xffffffffu, v, o);
    return v;
}
__device__ __forceinline__ float warpMax(float v) {
    #pragma unroll
    for (int o = 16; o; o >>= 1) v = fmaxf(v, __shfl_xor_sync(0xffffffffu, v, o));
    return v;
}
__device__ __forceinline__ float blockReduceSum(float v, float* red) {
    int lane = threadIdx.x & 31, w = threadIdx.x >> 5;
    v = warpSum(v);
    if (lane == 0) red[w] = v;
    __syncthreads();
    if (w == 0) {
        float r = (lane < (int)(blockDim.x >> 5)) ? red[lane] : 0.0f;
        r = warpSum(r);
        if (lane == 0) red[0] = r;
    }
    __syncthreads();
    float out = red[0];
    __syncthreads();
    return out;
}
__device__ __forceinline__ float blockReduceMax(float v, float* red) {
    int lane = threadIdx.x & 31, w = threadIdx.x >> 5;
    v = warpMax(v);
    if (lane == 0) red[w] = v;
    __syncthreads();
    if (w == 0) {
        float r = (lane < (int)(blockDim.x >> 5)) ? red[lane] : -INFINITY;
        r = warpMax(r);
        if (lane == 0) red[0] = r;
    }
    __syncthreads();
    float out = red[0];
    __syncthreads();
    return out;
}

// ---------------- embedding + rmsnorm ----------------
__global__ void embed_rmsnorm_kernel(const int* __restrict__ ids,
                                     const float* __restrict__ wte,
                                     float* __restrict__ out) {
    __shared__ float red[32];
    int t = blockIdx.x;
    const float* row = wte + (size_t)ids[t] * HIDDEN;
    float v[4]; float ss = 0.0f;
    #pragma unroll
    for (int i = 0; i < 4; i++) { v[i] = row[threadIdx.x + i * 256]; ss += v[i] * v[i]; }
    ss = blockReduceSum(ss, red);
    float sc = rsqrtf(ss * (1.0f / HIDDEN) + EPSV);
    #pragma unroll
    for (int i = 0; i < 4; i++)
        out[(size_t)t * HIDDEN + threadIdx.x + i * 256] = v[i] * sc;
}

__global__ void rmsnorm_kernel(const float* __restrict__ in, float* __restrict__ out) {
    __shared__ float red[32];
    int t = blockIdx.x;
    const float* row = in + (size_t)t * HIDDEN;
    float v[4]; float ss = 0.0f;
    #pragma unroll
    for (int i = 0; i < 4; i++) { v[i] = row[threadIdx.x + i * 256]; ss += v[i] * v[i]; }
    ss = blockReduceSum(ss, red);
    float sc = rsqrtf(ss * (1.0f / HIDDEN) + EPSV);
    #pragma unroll
    for (int i = 0; i < 4; i++)
        out[(size_t)t * HIDDEN + threadIdx.x + i * 256] = v[i] * sc;
}

// ---------------- rope tables ----------------
__global__ void rope_init_kernel(float* __restrict__ ctab, float* __restrict__ stab) {
    int t = blockIdx.x, i = threadIdx.x;  // i in [0,32)
    float invf = (float)pow(10000.0, -(double)(2 * i) / (double)HD);
    float ang = (float)t * invf;
    float s, c;
    sincosf(ang, &s, &c);
    ctab[t * 32 + i] = c;
    stab[t * 32 + i] = s;
}

// ---------------- per-head rmsnorm + rope on q,k ----------------
__global__ void qknorm_rope_kernel(float* __restrict__ qkv,
                                   const float* __restrict__ ctab,
                                   const float* __restrict__ stab) {
    int t = blockIdx.x, h = blockIdx.y, w = blockIdx.z;
    float* p = qkv + (size_t)t * (3 * HIDDEN) + (size_t)w * HIDDEN + h * HD;
    int i = threadIdx.x;
    float x0 = p[2 * i], x1 = p[2 * i + 1];
    float ss = warpSum(x0 * x0 + x1 * x1);
    float sc = rsqrtf(ss * (1.0f / HD) + EPSV);
    x0 *= sc; x1 *= sc;
    float c = ctab[t * 32 + i], s = stab[t * 32 + i];
    p[2 * i]     = x1 * c - x0 * s;
    p[2 * i + 1] = x1 * s + x0 * c;
}

// ---------------- attention: scores + softmax (causal) ----------------
__global__ void attn_scores_kernel(const float* __restrict__ qkv,
                                   float* __restrict__ scores) {
    __shared__ float q[HD];
    __shared__ float red[32];
    int i = blockIdx.x, h = blockIdx.y;
    int tid = threadIdx.x;
    int nk = i + 1;
    if (tid < HD) q[tid] = qkv[(size_t)i * (3 * HIDDEN) + h * HD + tid];
    __syncthreads();

    float sv[8];
    float lmax = -INFINITY;
    int cnt = 0;
    for (int j = tid; j < nk; j += 256) {
        const float4* k4 = (const float4*)(qkv + (size_t)j * (3 * HIDDEN) + HIDDEN + h * HD);
        float d = 0.0f;
        #pragma unroll
        for (int c4 = 0; c4 < HD / 4; c4++) {
            float4 kv = k4[c4];
            d += q[4 * c4 + 0] * kv.x + q[4 * c4 + 1] * kv.y
               + q[4 * c4 + 2] * kv.z + q[4 * c4 + 3] * kv.w;
        }
        d *= 0.125f;
        sv[cnt++] = d;
        lmax = fmaxf(lmax, d);
    }
    float m = blockReduceMax(lmax, red);
    float lsum = 0.0f;
    for (int c = 0; c < cnt; c++) { sv[c] = expf(sv[c] - m); lsum += sv[c]; }
    float s = blockReduceSum(lsum, red);
    float rinv = 1.0f / s;
    cnt = 0;
    for (int j = tid; j < nk; j += 256)
        scores[((size_t)h * SEQ + i) * SEQ + j] = sv[cnt++] * rinv;
}

// ---------------- attention: O = P @ V ----------------
__global__ void attn_av_kernel(const float* __restrict__ qkv,
                               const float* __restrict__ scores,
                               float* __restrict__ out) {
    __shared__ float sa[4][HD];
    int i = blockIdx.x, h = blockIdx.y;
    int tid = threadIdx.x;
    int d = tid & 63, part = tid >> 6;
    const float* pr = scores + ((size_t)h * SEQ + i) * SEQ;
    const float* vb = qkv + 2 * HIDDEN + h * HD + d;
    float acc = 0.0f;
    for (int j = part; j <= i; j += 4)
        acc += pr[j] * vb[(size_t)j * (3 * HIDDEN)];
    sa[part][d] = acc;
    __syncthreads();
    if (part == 0)
        out[(size_t)i * HIDDEN + h * HD + d] = sa[0][d] + sa[1][d] + sa[2][d] + sa[3][d];
}

// ================= HMMA (mma.sync) bf16-split GEMM =================
// C[M,N] = A[M,K] @ B[N,K]^T, fp32 in/out. bf16 2-term split: C += Ah*Bh + Ah*Bl + Al*Bh.
// Tile 128x128x32, 256 threads, 8 warps of 64x32. Row stride 40 bf16 -> conflict-free ldmatrix.
// EPI 0: C = AB^T   EPI 1: C = R + AB^T   EPI 2: C = relu(AB^T)^2
#define RS 40

__device__ __forceinline__ void mma_bf16(float* c, const uint32_t* a, const uint32_t* b) {
    asm volatile(
        "mma.sync.aligned.m16n8k16.row.col.f32.bf16.bf16.f32 "
        "{%0,%1,%2,%3}, {%4,%5,%6,%7}, {%8,%9}, {%0,%1,%2,%3};"
        : "+f"(c[0]), "+f"(c[1]), "+f"(c[2]), "+f"(c[3])
        : "r"(a[0]), "r"(a[1]), "r"(a[2]), "r"(a[3]), "r"(b[0]), "r"(b[1]));
}
__device__ __forceinline__ void ldmx4(uint32_t* d, uint32_t addr) {
    asm volatile("ldmatrix.sync.aligned.m8n8.x4.shared.b16 {%0,%1,%2,%3}, [%4];"
                 : "=r"(d[0]), "=r"(d[1]), "=r"(d[2]), "=r"(d[3]) : "r"(addr));
}
__device__ __forceinline__ void split4(float4 f, uint2& h, uint2& l) {
    __nv_bfloat162 h0 = __floats2bfloat162_rn(f.x, f.y);
    __nv_bfloat162 h1 = __floats2bfloat162_rn(f.z, f.w);
    __nv_bfloat162 l0 = __floats2bfloat162_rn(f.x - __bfloat162float(h0.x),
                                              f.y - __bfloat162float(h0.y));
    __nv_bfloat162 l1 = __floats2bfloat162_rn(f.z - __bfloat162float(h1.x),
                                              f.w - __bfloat162float(h1.y));
    h.x = *(uint32_t*)&h0; h.y = *(uint32_t*)&h1;
    l.x = *(uint32_t*)&l0; l.y = *(uint32_t*)&l1;
}

template <int EPI>
__global__ void __launch_bounds__(256, 1)
gemm_hmma_kernel(const float* __restrict__ A, const float* __restrict__ B,
                 float* __restrict__ C, const float* __restrict__ R,
                 int M, int N, int K) {
    __shared__ uint16_t sAh[128 * RS], sAl[128 * RS], sBh[128 * RS], sBl[128 * RS];

    int tid = threadIdx.x, lane = tid & 31, wid = tid >> 5;
    int wm = wid >> 2, wn = wid & 3;
    int bm = blockIdx.y * 128, bn = blockIdx.x * 128;
    int r = tid >> 1, hf = (tid & 1) * 16;
    bool bok = (bn + r) < N;

    const float* Aptr = A + (size_t)(bm + r) * K + hf;
    const float* Bptr = B + (size_t)(bn + r) * K + hf;

    uint32_t uAh = smem_u32(sAh), uAl = smem_u32(sAl);
    uint32_t uBh = smem_u32(sBh), uBl = smem_u32(sBl);

    // ldmatrix per-lane address offsets (bytes)
    uint32_t aoff = (uint32_t)(((wm * 64 + (lane & 15)) * RS + ((lane >> 4) & 1) * 8) * 2);
    uint32_t boff = (uint32_t)(((wn * 32 + ((lane >> 4) & 1) * 8 + (lane & 7)) * RS
                                + ((lane >> 3) & 1) * 8) * 2);
    uint32_t soff = (uint32_t)((r * RS + hf) * 2);  // sts base (bytes)

    float acc[4][4][4] = {};
    float4 pfA[4], pfB[4];

    int nCh = K >> 5;
    // prefetch chunk 0
    #pragma unroll
    for (int g = 0; g < 4; g++) {
        pfA[g] = *(const float4*)(Aptr + g * 4);
        pfB[g] = bok ? *(const float4*)(Bptr + g * 4) : make_float4(0.f, 0.f, 0.f, 0.f);
    }

    for (int s = 0; s < nCh; s++) {
        // store current chunk to smem (split hi/lo)
        #pragma unroll
        for (int g = 0; g < 4; g++) {
            uint2 h, l;
            split4(pfA[g], h, l);
            *(uint2*)((char*)sAh + soff + g * 8) = h;
            *(uint2*)((char*)sAl + soff + g * 8) = l;
            split4(pfB[g], h, l);
            *(uint2*)((char*)sBh + soff + g * 8) = h;
            *(uint2*)((char*)sBl + soff + g * 8) = l;
        }
        __syncthreads();

        // prefetch next chunk (overlaps with MMA below)
        if (s + 1 < nCh) {
            int k0 = (s + 1) << 5;
            #pragma unroll
            for (int g = 0; g < 4; g++) {
                pfA[g] = *(const float4*)(Aptr + k0 + g * 4);
                pfB[g] = bok ? *(const float4*)(Bptr + k0 + g * 4) : make_float4(0.f, 0.f, 0.f, 0.f);
            }
        }

        // MMA over this chunk: 2 k-steps x 3 passes
        #pragma unroll
        for (int ks = 0; ks < 2; ks++) {
            uint32_t k2 = (uint32_t)(ks * 32);  // 16 elems * 2B
            uint32_t aH[4][4], aL[4][4], bH[2][4], bL[2][4];
            #pragma unroll
            for (int mt = 0; mt < 4; mt++) ldmx4(aH[mt], uAh + aoff + mt * (16 * RS * 2) + k2);
            #pragma unroll
            for (int np = 0; np < 2; np++) ldmx4(bH[np], uBh + boff + np * (16 * RS * 2) + k2);
            #pragma unroll
            for (int mt = 0; mt < 4; mt++)
                #pragma unroll
                for (int nt = 0; nt < 4; nt++)
                    mma_bf16(acc[mt][nt], aH[mt], &bH[nt >> 1][(nt & 1) * 2]);
            #pragma unroll
            for (int np = 0; np < 2; np++) ldmx4(bL[np], uBl + boff + np * (16 * RS * 2) + k2);
            #pragma unroll
            for (int mt = 0; mt < 4; mt++)
                #pragma unroll
                for (int nt = 0; nt < 4; nt++)
                    mma_bf16(acc[mt][nt], aH[mt], &bL[nt >> 1][(nt & 1) * 2]);
            #pragma unroll
            for (int mt = 0; mt < 4; mt++) ldmx4(aL[mt], uAl + aoff + mt * (16 * RS * 2) + k2);
            #pragma unroll
            for (int mt = 0; mt < 4; mt++)
                #pragma unroll
                for (int nt = 0; nt < 4; nt++)
                    mma_bf16(acc[mt][nt], aL[mt], &bH[nt >> 1][(nt & 1) * 2]);
        }
        __syncthreads();
    }

    // epilogue
    #pragma unroll
    for (int mt = 0; mt < 4; mt++) {
        int row = bm + wm * 64 + mt * 16 + (lane >> 2);
        #pragma unroll
        for (int nt = 0; nt < 4; nt++) {
            int col = bn + wn * 32 + nt * 8 + (lane & 3) * 2;
            if (col < N) {
                float* c = acc[mt][nt];
                float2 v0 = make_float2(c[0], c[1]);
                float2 v1 = make_float2(c[2], c[3]);
                if (EPI == 1) {
                    float2 r0 = *(const float2*)(R + (size_t)row * N + col);
                    float2 r1 = *(const float2*)(R + (size_t)(row + 8) * N + col);
                    v0.x += r0.x; v0.y += r0.y; v1.x += r1.x; v1.y += r1.y;
                }
                if (EPI == 2) {
                    v0.x = fmaxf(v0.x, 0.f); v0.x *= v0.x;
                    v0.y = fmaxf(v0.y, 0.f); v0.y *= v0.y;
                    v1.x = fmaxf(v1.x, 0.f); v1.x *= v1.x;
                    v1.y = fmaxf(v1.y, 0.f); v1.y *= v1.y;
                }
                *(float2*)(C + (size_t)row * N + col) = v0;
                *(float2*)(C + (size_t)(row + 8) * N + col) = v1;
            }
        }
    }
}

// ---------------- host launcher ----------------
extern "C" void kernel_launch(void* const* d_in, const int* in_sizes, int n_in,
                              void* d_out, int out_size) {
    const int*   ids  = (const int*)d_in[0];
    const float* wte  = (const float*)d_in[1];
    const float* wqkv = (const float*)d_in[2];
    const float* wo   = (const float*)d_in[3];
    const float* w1   = (const float*)d_in[4];
    const float* w2   = (const float*)d_in[5];
    const float* lm   = (const float*)d_in[6];
    float* out = (float*)d_out;

    float *px, *ph, *pqkv, *patt, *pmid, *pscr, *pcos, *psin;
    cudaGetSymbolAddress((void**)&px,   g_x);
    cudaGetSymbolAddress((void**)&ph,   g_h);
    cudaGetSymbolAddress((void**)&pqkv, g_qkv);
    cudaGetSymbolAddress((void**)&patt, g_att);
    cudaGetSymbolAddress((void**)&pmid, g_mid);
    cudaGetSymbolAddress((void**)&pscr, g_scores);
    cudaGetSymbolAddress((void**)&pcos, g_cos);
    cudaGetSymbolAddress((void**)&psin, g_sin);

    rope_init_kernel<<<SEQ, 32>>>(pcos, psin);
    embed_rmsnorm_kernel<<<SEQ, 256>>>(ids, wte, px);

    for (int l = 0; l < NL; l++) {
        const float* wqkv_l = wqkv + (size_t)l * 3 * HIDDEN * HIDDEN;
        const float* wo_l   = wo   + (size_t)l * HIDDEN * HIDDEN;
        const float* w1_l   = w1   + (size_t)l * FFN * HIDDEN;
        const float* w2_l   = w2   + (size_t)l * HIDDEN * FFN;

        rmsnorm_kernel<<<SEQ, 256>>>(px, ph);
        gemm_hmma_kernel<0><<<dim3((3 * HIDDEN) / 128, SEQ / 128), 256>>>(
            ph, wqkv_l, pqkv, nullptr, SEQ, 3 * HIDDEN, HIDDEN);
        qknorm_rope_kernel<<<dim3(SEQ, NH, 2), 32>>>(pqkv, pcos, psin);
        attn_scores_kernel<<<dim3(SEQ, NH), 256>>>(pqkv, pscr);
        attn_av_kernel<<<dim3(SEQ, NH), 256>>>(pqkv, pscr, patt);
        gemm_hmma_kernel<1><<<dim3(HIDDEN / 128, SEQ / 128), 256>>>(
            patt, wo_l, px, px, SEQ, HIDDEN, HIDDEN);

        rmsnorm_kernel<<<SEQ, 256>>>(px, ph);
        gemm_hmma_kernel<2><<<dim3(FFN / 128, SEQ / 128), 256>>>(
            ph, w1_l, pmid, nullptr, SEQ, FFN, HIDDEN);
        gemm_hmma_kernel<1><<<dim3(HIDDEN / 128, SEQ / 128), 256>>>(
            pmid, w2_l, px, px, SEQ, HIDDEN, FFN);
    }

    rmsnorm_kernel<<<SEQ, 256>>>(px, ph);
    gemm_hmma_kernel<0><<<dim3((VOCABSZ + 127) / 128, SEQ / 128), 256>>>(
        ph, lm, out, nullptr, SEQ, VOCABSZ, HIDDEN);
}

// round 5
// speedup vs baseline: 7.4757x; 3.2284x over previous
#include <cuda_runtime.h>
#include <cuda_bf16.h>
#include <math.h>
#include <stdint.h>

#define SEQ     2048
#define HIDDEN  1024
#define NH      16
#define HD      64
#define NL      8
#define VOCABSZ 50272
#define FFN     4096
#define EPSV    1e-5f

// ---------------- scratch (device globals; no allocs allowed) ----------------
__device__ float g_x  [(size_t)SEQ * HIDDEN];
__device__ float g_h  [(size_t)SEQ * HIDDEN];
__device__ float g_qkv[(size_t)SEQ * 3 * HIDDEN];
__device__ float g_att[(size_t)SEQ * HIDDEN];
__device__ float g_mid[(size_t)SEQ * FFN];
__device__ float g_cos[(size_t)SEQ * (HD / 2)];
__device__ float g_sin[(size_t)SEQ * (HD / 2)];

// ---------------- helpers ----------------
__device__ __forceinline__ uint32_t smem_u32(const void* p) {
    uint32_t a;
    asm("{ .reg .u64 t; cvta.to.shared.u64 t, %1; cvt.u32.u64 %0, t; }" : "=r"(a) : "l"(p));
    return a;
}
__device__ __forceinline__ float warpSum(float v) {
    #pragma unroll
    for (int o = 16; o; o >>= 1) v += __shfl_xor_sync(0xffffffffu, v, o);
    return v;
}
__device__ __forceinline__ float blockReduceSum(float v, float* red) {
    int lane = threadIdx.x & 31, w = threadIdx.x >> 5;
    v = warpSum(v);
    if (lane == 0) red[w] = v;
    __syncthreads();
    if (w == 0) {
        float r = (lane < (int)(blockDim.x >> 5)) ? red[lane] : 0.0f;
        r = warpSum(r);
        if (lane == 0) red[0] = r;
    }
    __syncthreads();
    float out = red[0];
    __syncthreads();
    return out;
}

// ---------------- embedding + rmsnorm ----------------
__global__ void embed_rmsnorm_kernel(const int* __restrict__ ids,
                                     const float* __restrict__ wte,
                                     float* __restrict__ out) {
    __shared__ float red[32];
    int t = blockIdx.x;
    const float* row = wte + (size_t)ids[t] * HIDDEN;
    float v[4]; float ss = 0.0f;
    #pragma unroll
    for (int i = 0; i < 4; i++) { v[i] = row[threadIdx.x + i * 256]; ss += v[i] * v[i]; }
    ss = blockReduceSum(ss, red);
    float sc = rsqrtf(ss * (1.0f / HIDDEN) + EPSV);
    #pragma unroll
    for (int i = 0; i < 4; i++)
        out[(size_t)t * HIDDEN + threadIdx.x + i * 256] = v[i] * sc;
}

__global__ void rmsnorm_kernel(const float* __restrict__ in, float* __restrict__ out) {
    __shared__ float red[32];
    int t = blockIdx.x;
    const float* row = in + (size_t)t * HIDDEN;
    float v[4]; float ss = 0.0f;
    #pragma unroll
    for (int i = 0; i < 4; i++) { v[i] = row[threadIdx.x + i * 256]; ss += v[i] * v[i]; }
    ss = blockReduceSum(ss, red);
    float sc = rsqrtf(ss * (1.0f / HIDDEN) + EPSV);
    #pragma unroll
    for (int i = 0; i < 4; i++)
        out[(size_t)t * HIDDEN + threadIdx.x + i * 256] = v[i] * sc;
}

// ---------------- rope tables ----------------
__global__ void rope_init_kernel(float* __restrict__ ctab, float* __restrict__ stab) {
    int t = blockIdx.x, i = threadIdx.x;
    float invf = (float)pow(10000.0, -(double)(2 * i) / (double)HD);
    float ang = (float)t * invf;
    float s, c;
    sincosf(ang, &s, &c);
    ctab[t * 32 + i] = c;
    stab[t * 32 + i] = s;
}

// ---------------- per-head rmsnorm + rope on q,k ----------------
__global__ void qknorm_rope_kernel(float* __restrict__ qkv,
                                   const float* __restrict__ ctab,
                                   const float* __restrict__ stab) {
    int t = blockIdx.x, h = blockIdx.y, w = blockIdx.z;
    float* p = qkv + (size_t)t * (3 * HIDDEN) + (size_t)w * HIDDEN + h * HD;
    int i = threadIdx.x;
    float x0 = p[2 * i], x1 = p[2 * i + 1];
    float ss = warpSum(x0 * x0 + x1 * x1);
    float sc = rsqrtf(ss * (1.0f / HD) + EPSV);
    x0 *= sc; x1 *= sc;
    float c = ctab[t * 32 + i], s = stab[t * 32 + i];
    p[2 * i]     = x1 * c - x0 * s;
    p[2 * i + 1] = x1 * s + x0 * c;
}

// ================= shared MMA utils =================
#define RS 40

__device__ __forceinline__ void mma_bf16(float* c, const uint32_t* a, const uint32_t* b) {
    asm volatile(
        "mma.sync.aligned.m16n8k16.row.col.f32.bf16.bf16.f32 "
        "{%0,%1,%2,%3}, {%4,%5,%6,%7}, {%8,%9}, {%0,%1,%2,%3};"
        : "+f"(c[0]), "+f"(c[1]), "+f"(c[2]), "+f"(c[3])
        : "r"(a[0]), "r"(a[1]), "r"(a[2]), "r"(a[3]), "r"(b[0]), "r"(b[1]));
}
__device__ __forceinline__ void ldmx4(uint32_t* d, uint32_t addr) {
    asm volatile("ldmatrix.sync.aligned.m8n8.x4.shared.b16 {%0,%1,%2,%3}, [%4];"
                 : "=r"(d[0]), "=r"(d[1]), "=r"(d[2]), "=r"(d[3]) : "r"(addr));
}
__device__ __forceinline__ void ldmx4t(uint32_t* d, uint32_t addr) {
    asm volatile("ldmatrix.sync.aligned.m8n8.x4.trans.shared.b16 {%0,%1,%2,%3}, [%4];"
                 : "=r"(d[0]), "=r"(d[1]), "=r"(d[2]), "=r"(d[3]) : "r"(addr));
}
__device__ __forceinline__ void split4(float4 f, uint2& h, uint2& l) {
    __nv_bfloat162 h0 = __floats2bfloat162_rn(f.x, f.y);
    __nv_bfloat162 h1 = __floats2bfloat162_rn(f.z, f.w);
    __nv_bfloat162 l0 = __floats2bfloat162_rn(f.x - __bfloat162float(h0.x),
                                              f.y - __bfloat162float(h0.y));
    __nv_bfloat162 l1 = __floats2bfloat162_rn(f.z - __bfloat162float(h1.x),
                                              f.w - __bfloat162float(h1.y));
    h.x = *(uint32_t*)&h0; h.y = *(uint32_t*)&h1;
    l.x = *(uint32_t*)&l0; l.y = *(uint32_t*)&l1;
}

// ================= fused flash attention (bf16-split HMMA) =================
// grid (SEQ/64, NH), 128 threads (4 warps x 16 q-rows). BM=BN=64, hd=64.
// Dynamic smem: 6 tiles of 64 x FRS bf16 (row stride 72 elems = 144B -> conflict-free
// ldmatrix: row starts i*144 mod 128 = i*16, 8 distinct 16B slots per octet).
#define FRS       72
#define FT_BYTES  (64 * FRS * 2)          // 9216
#define FLASH_SMEM (6 * FT_BYTES)         // 55296

__global__ void __launch_bounds__(128, 2)
flash_attn_kernel(const float* __restrict__ qkv, float* __restrict__ out) {
    extern __shared__ char fsm[];
    char* pQh = fsm;
    char* pQl = fsm + FT_BYTES;
    char* pKh = fsm + 2 * FT_BYTES;
    char* pKl = fsm + 3 * FT_BYTES;
    char* pVh = fsm + 4 * FT_BYTES;
    char* pVl = fsm + 5 * FT_BYTES;

    int tid = threadIdx.x, lane = tid & 31, wid = tid >> 5;
    int h = blockIdx.y;
    int qt = (int)gridDim.x - 1 - (int)blockIdx.x;   // big tiles first (load balance)
    int bm = qt * 64;

    int r = tid >> 1, c0 = (tid & 1) * 32;
    uint32_t soff = (uint32_t)((r * FRS + c0) * 2);

    uint32_t uQh = smem_u32(pQh), uQl = smem_u32(pQl);
    uint32_t uKh = smem_u32(pKh), uKl = smem_u32(pKl);
    uint32_t uVh = smem_u32(pVh), uVl = smem_u32(pVl);

    // ---- load Q tile (rows bm..bm+63), split hi/lo ----
    {
        const float* Qrow = qkv + (size_t)(bm + r) * (3 * HIDDEN) + h * HD + c0;
        #pragma unroll
        for (int g = 0; g < 8; g++) {
            uint2 hh, ll;
            split4(*(const float4*)(Qrow + g * 4), hh, ll);
            *(uint2*)(pQh + soff + g * 8) = hh;
            *(uint2*)(pQl + soff + g * 8) = ll;
        }
    }
    __syncthreads();

    // ---- Q fragments to registers ----
    uint32_t qh[4][4], ql[4][4];
    {
        uint32_t qoff = (uint32_t)(((wid * 16 + (lane & 15)) * FRS + ((lane >> 4) & 1) * 8) * 2);
        #pragma unroll
        for (int ks = 0; ks < 4; ks++) {
            ldmx4(qh[ks], uQh + qoff + ks * 32);
            ldmx4(ql[ks], uQl + qoff + ks * 32);
        }
    }

    float o[8][4] = {};
    float m[2] = {-INFINITY, -INFINITY};
    float l[2] = {0.0f, 0.0f};

    for (int jt = 0; jt <= qt; jt++) {
        __syncthreads();
        // ---- load K,V tile jt ----
        {
            const float* Krow = qkv + (size_t)(jt * 64 + r) * (3 * HIDDEN) + HIDDEN + h * HD + c0;
            const float* Vrow = Krow + HIDDEN;
            #pragma unroll
            for (int g = 0; g < 8; g++) {
                uint2 hh, ll;
                split4(*(const float4*)(Krow + g * 4), hh, ll);
                *(uint2*)(pKh + soff + g * 8) = hh;
                *(uint2*)(pKl + soff + g * 8) = ll;
                split4(*(const float4*)(Vrow + g * 4), hh, ll);
                *(uint2*)(pVh + soff + g * 8) = hh;
                *(uint2*)(pVl + soff + g * 8) = ll;
            }
        }
        __syncthreads();

        // ---- scores S = Q K^T * 0.125 ----
        float s[8][4] = {};
        uint32_t bbase = (uint32_t)(((((lane >> 4) & 1) * 8 + (lane & 7)) * FRS
                                     + ((lane >> 3) & 1) * 8) * 2);
        #pragma unroll
        for (int ks = 0; ks < 4; ks++) {
            #pragma unroll
            for (int nb = 0; nb < 4; nb++) {
                uint32_t kh[4], kl[4];
                uint32_t bo = bbase + (uint32_t)(nb * 16 * FRS * 2) + (uint32_t)(ks * 32);
                ldmx4(kh, uKh + bo);
                ldmx4(kl, uKl + bo);
                mma_bf16(s[nb * 2],     qh[ks], kh + 0);
                mma_bf16(s[nb * 2 + 1], qh[ks], kh + 2);
                mma_bf16(s[nb * 2],     qh[ks], kl + 0);
                mma_bf16(s[nb * 2 + 1], qh[ks], kl + 2);
                mma_bf16(s[nb * 2],     ql[ks], kh + 0);
                mma_bf16(s[nb * 2 + 1], ql[ks], kh + 2);
            }
        }
        #pragma unroll
        for (int nt = 0; nt < 8; nt++)
            #pragma unroll
            for (int c = 0; c < 4; c++) s[nt][c] *= 0.125f;

        // ---- causal mask (diag tile only) ----
        if (jt == qt) {
            int q0 = wid * 16 + (lane >> 2);
            int q1 = q0 + 8;
            #pragma unroll
            for (int nt = 0; nt < 8; nt++) {
                int j0 = nt * 8 + (lane & 3) * 2;
                if (j0     > q0) s[nt][0] = -INFINITY;
                if (j0 + 1 > q0) s[nt][1] = -INFINITY;
                if (j0     > q1) s[nt][2] = -INFINITY;
                if (j0 + 1 > q1) s[nt][3] = -INFINITY;
            }
        }

        // ---- online softmax (2 row halves per thread) ----
        #pragma unroll
        for (int hh = 0; hh < 2; hh++) {
            float rm = -INFINITY;
            #pragma unroll
            for (int nt = 0; nt < 8; nt++)
                rm = fmaxf(rm, fmaxf(s[nt][2 * hh], s[nt][2 * hh + 1]));
            rm = fmaxf(rm, __shfl_xor_sync(0xffffffffu, rm, 1));
            rm = fmaxf(rm, __shfl_xor_sync(0xffffffffu, rm, 2));
            float mnew = fmaxf(m[hh], rm);
            float corr = __expf(m[hh] - mnew);
            float rs = 0.0f;
            #pragma unroll
            for (int nt = 0; nt < 8; nt++) {
                float p0 = __expf(s[nt][2 * hh]     - mnew);
                float p1 = __expf(s[nt][2 * hh + 1] - mnew);
                s[nt][2 * hh] = p0; s[nt][2 * hh + 1] = p1;
                rs += p0 + p1;
            }
            rs += __shfl_xor_sync(0xffffffffu, rs, 1);
            rs += __shfl_xor_sync(0xffffffffu, rs, 2);
            l[hh] = l[hh] * corr + rs;
            m[hh] = mnew;
            #pragma unroll
            for (int dt = 0; dt < 8; dt++) {
                o[dt][2 * hh] *= corr; o[dt][2 * hh + 1] *= corr;
            }
        }

        // ---- O += P V  (P split hi/lo from registers, V via ldmatrix.trans) ----
        #pragma unroll
        for (int jks = 0; jks < 4; jks++) {
            float* ce = s[2 * jks];
            float* co = s[2 * jks + 1];
            uint32_t pa[4], pb[4];
            {
                __nv_bfloat162 h0 = __floats2bfloat162_rn(ce[0], ce[1]);
                __nv_bfloat162 h1 = __floats2bfloat162_rn(ce[2], ce[3]);
                __nv_bfloat162 h2 = __floats2bfloat162_rn(co[0], co[1]);
                __nv_bfloat162 h3 = __floats2bfloat162_rn(co[2], co[3]);
                pa[0] = *(uint32_t*)&h0; pa[1] = *(uint32_t*)&h1;
                pa[2] = *(uint32_t*)&h2; pa[3] = *(uint32_t*)&h3;
                __nv_bfloat162 e0 = __floats2bfloat162_rn(ce[0] - __bfloat162float(h0.x),
                                                          ce[1] - __bfloat162float(h0.y));
                __nv_bfloat162 e1 = __floats2bfloat162_rn(ce[2] - __bfloat162float(h1.x),
                                                          ce[3] - __bfloat162float(h1.y));
                __nv_bfloat162 e2 = __floats2bfloat162_rn(co[0] - __bfloat162float(h2.x),
                                                          co[1] - __bfloat162float(h2.y));
                __nv_bfloat162 e3 = __floats2bfloat162_rn(co[2] - __bfloat162float(h3.x),
                                                          co[3] - __bfloat162float(h3.y));
                pb[0] = *(uint32_t*)&e0; pb[1] = *(uint32_t*)&e1;
                pb[2] = *(uint32_t*)&e2; pb[3] = *(uint32_t*)&e3;
            }
            uint32_t vbase = (uint32_t)(((jks * 16 + (lane & 15)) * FRS
                                         + ((lane >> 4) & 1) * 8) * 2);
            #pragma unroll
            for (int db = 0; db < 4; db++) {
                uint32_t vh[4], vl[4];
                uint32_t vo = vbase + (uint32_t)(db * 32);
                ldmx4t(vh, uVh + vo);
                ldmx4t(vl, uVl + vo);
                mma_bf16(o[db * 2],     pa, vh + 0);
                mma_bf16(o[db * 2 + 1], pa, vh + 2);
                mma_bf16(o[db * 2],     pa, vl + 0);
                mma_bf16(o[db * 2 + 1], pa, vl + 2);
                mma_bf16(o[db * 2],     pb, vh + 0);
                mma_bf16(o[db * 2 + 1], pb, vh + 2);
            }
        }
    }

    // ---- finalize and write ----
    float inv0 = 1.0f / l[0], inv1 = 1.0f / l[1];
    int row0 = bm + wid * 16 + (lane >> 2);
    #pragma unroll
    for (int dt = 0; dt < 8; dt++) {
        int col = h * HD + dt * 8 + (lane & 3) * 2;
        *(float2*)(out + (size_t)row0 * HIDDEN + col) =
            make_float2(o[dt][0] * inv0, o[dt][1] * inv0);
        *(float2*)(out + (size_t)(row0 + 8) * HIDDEN + col) =
            make_float2(o[dt][2] * inv1, o[dt][3] * inv1);
    }
}

// ================= HMMA (mma.sync) bf16-split GEMM =================
template <int EPI>
__global__ void __launch_bounds__(256, 1)
gemm_hmma_kernel(const float* __restrict__ A, const float* __restrict__ B,
                 float* __restrict__ C, const float* __restrict__ R,
                 int M, int N, int K) {
    __shared__ uint16_t sAh[128 * RS], sAl[128 * RS], sBh[128 * RS], sBl[128 * RS];

    int tid = threadIdx.x, lane = tid & 31, wid = tid >> 5;
    int wm = wid >> 2, wn = wid & 3;
    int bm = blockIdx.y * 128, bn = blockIdx.x * 128;
    int r = tid >> 1, hf = (tid & 1) * 16;
    bool bok = (bn + r) < N;

    const float* Aptr = A + (size_t)(bm + r) * K + hf;
    const float* Bptr = B + (size_t)(bn + r) * K + hf;

    uint32_t uAh = smem_u32(sAh), uAl = smem_u32(sAl);
    uint32_t uBh = smem_u32(sBh), uBl = smem_u32(sBl);

    uint32_t aoff = (uint32_t)(((wm * 64 + (lane & 15)) * RS + ((lane >> 4) & 1) * 8) * 2);
    uint32_t boff = (uint32_t)(((wn * 32 + ((lane >> 4) & 1) * 8 + (lane & 7)) * RS
                                + ((lane >> 3) & 1) * 8) * 2);
    uint32_t soff = (uint32_t)((r * RS + hf) * 2);

    float acc[4][4][4] = {};
    float4 pfA[4], pfB[4];

    int nCh = K >> 5;
    #pragma unroll
    for (int g = 0; g < 4; g++) {
        pfA[g] = *(const float4*)(Aptr + g * 4);
        pfB[g] = bok ? *(const float4*)(Bptr + g * 4) : make_float4(0.f, 0.f, 0.f, 0.f);
    }

    for (int s = 0; s < nCh; s++) {
        #pragma unroll
        for (int g = 0; g < 4; g++) {
            uint2 h, l;
            split4(pfA[g], h, l);
            *(uint2*)((char*)sAh + soff + g * 8) = h;
            *(uint2*)((char*)sAl + soff + g * 8) = l;
            split4(pfB[g], h, l);
            *(uint2*)((char*)sBh + soff + g * 8) = h;
            *(uint2*)((char*)sBl + soff + g * 8) = l;
        }
        __syncthreads();

        if (s + 1 < nCh) {
            int k0 = (s + 1) << 5;
            #pragma unroll
            for (int g = 0; g < 4; g++) {
                pfA[g] = *(const float4*)(Aptr + k0 + g * 4);
                pfB[g] = bok ? *(const float4*)(Bptr + k0 + g * 4) : make_float4(0.f, 0.f, 0.f, 0.f);
            }
        }

        #pragma unroll
        for (int ks = 0; ks < 2; ks++) {
            uint32_t k2 = (uint32_t)(ks * 32);
            uint32_t aH[4][4], aL[4][4], bH[2][4], bL[2][4];
            #pragma unroll
            for (int mt = 0; mt < 4; mt++) ldmx4(aH[mt], uAh + aoff + mt * (16 * RS * 2) + k2);
            #pragma unroll
            for (int np = 0; np < 2; np++) ldmx4(bH[np], uBh + boff + np * (16 * RS * 2) + k2);
            #pragma unroll
            for (int mt = 0; mt < 4; mt++)
                #pragma unroll
                for (int nt = 0; nt < 4; nt++)
                    mma_bf16(acc[mt][nt], aH[mt], &bH[nt >> 1][(nt & 1) * 2]);
            #pragma unroll
            for (int np = 0; np < 2; np++) ldmx4(bL[np], uBl + boff + np * (16 * RS * 2) + k2);
            #pragma unroll
            for (int mt = 0; mt < 4; mt++)
                #pragma unroll
                for (int nt = 0; nt < 4; nt++)
                    mma_bf16(acc[mt][nt], aH[mt], &bL[nt >> 1][(nt & 1) * 2]);
            #pragma unroll
            for (int mt = 0; mt < 4; mt++) ldmx4(aL[mt], uAl + aoff + mt * (16 * RS * 2) + k2);
            #pragma unroll
            for (int mt = 0; mt < 4; mt++)
                #pragma unroll
                for (int nt = 0; nt < 4; nt++)
                    mma_bf16(acc[mt][nt], aL[mt], &bH[nt >> 1][(nt & 1) * 2]);
        }
        __syncthreads();
    }

    #pragma unroll
    for (int mt = 0; mt < 4; mt++) {
        int row = bm + wm * 64 + mt * 16 + (lane >> 2);
        #pragma unroll
        for (int nt = 0; nt < 4; nt++) {
            int col = bn + wn * 32 + nt * 8 + (lane & 3) * 2;
            if (col < N) {
                float* c = acc[mt][nt];
                float2 v0 = make_float2(c[0], c[1]);
                float2 v1 = make_float2(c[2], c[3]);
                if (EPI == 1) {
                    float2 r0 = *(const float2*)(R + (size_t)row * N + col);
                    float2 r1 = *(const float2*)(R + (size_t)(row + 8) * N + col);
                    v0.x += r0.x; v0.y += r0.y; v1.x += r1.x; v1.y += r1.y;
                }
                if (EPI == 2) {
                    v0.x = fmaxf(v0.x, 0.f); v0.x *= v0.x;
                    v0.y = fmaxf(v0.y, 0.f); v0.y *= v0.y;
                    v1.x = fmaxf(v1.x, 0.f); v1.x *= v1.x;
                    v1.y = fmaxf(v1.y, 0.f); v1.y *= v1.y;
                }
                *(float2*)(C + (size_t)row * N + col) = v0;
                *(float2*)(C + (size_t)(row + 8) * N + col) = v1;
            }
        }
    }
}

// ---------------- host launcher ----------------
extern "C" void kernel_launch(void* const* d_in, const int* in_sizes, int n_in,
                              void* d_out, int out_size) {
    const int*   ids  = (const int*)d_in[0];
    const float* wte  = (const float*)d_in[1];
    const float* wqkv = (const float*)d_in[2];
    const float* wo   = (const float*)d_in[3];
    const float* w1   = (const float*)d_in[4];
    const float* w2   = (const float*)d_in[5];
    const float* lm   = (const float*)d_in[6];
    float* out = (float*)d_out;

    float *px, *ph, *pqkv, *patt, *pmid, *pcos, *psin;
    cudaGetSymbolAddress((void**)&px,   g_x);
    cudaGetSymbolAddress((void**)&ph,   g_h);
    cudaGetSymbolAddress((void**)&pqkv, g_qkv);
    cudaGetSymbolAddress((void**)&patt, g_att);
    cudaGetSymbolAddress((void**)&pmid, g_mid);
    cudaGetSymbolAddress((void**)&pcos, g_cos);
    cudaGetSymbolAddress((void**)&psin, g_sin);

    cudaFuncSetAttribute(flash_attn_kernel,
                         cudaFuncAttributeMaxDynamicSharedMemorySize, FLASH_SMEM);

    rope_init_kernel<<<SEQ, 32>>>(pcos, psin);
    embed_rmsnorm_kernel<<<SEQ, 256>>>(ids, wte, px);

    for (int l = 0; l < NL; l++) {
        const float* wqkv_l = wqkv + (size_t)l * 3 * HIDDEN * HIDDEN;
        const float* wo_l   = wo   + (size_t)l * HIDDEN * HIDDEN;
        const float* w1_l   = w1   + (size_t)l * FFN * HIDDEN;
        const float* w2_l   = w2   + (size_t)l * HIDDEN * FFN;

        rmsnorm_kernel<<<SEQ, 256>>>(px, ph);
        gemm_hmma_kernel<0><<<dim3((3 * HIDDEN) / 128, SEQ / 128), 256>>>(
            ph, wqkv_l, pqkv, nullptr, SEQ, 3 * HIDDEN, HIDDEN);
        qknorm_rope_kernel<<<dim3(SEQ, NH, 2), 32>>>(pqkv, pcos, psin);
        flash_attn_kernel<<<dim3(SEQ / 64, NH), 128, FLASH_SMEM>>>(pqkv, patt);
        gemm_hmma_kernel<1><<<dim3(HIDDEN / 128, SEQ / 128), 256>>>(
            patt, wo_l, px, px, SEQ, HIDDEN, HIDDEN);

        rmsnorm_kernel<<<SEQ, 256>>>(px, ph);
        gemm_hmma_kernel<2><<<dim3(FFN / 128, SEQ / 128), 256>>>(
            ph, w1_l, pmid, nullptr, SEQ, FFN, HIDDEN);
        gemm_hmma_kernel<1><<<dim3(HIDDEN / 128, SEQ / 128), 256>>>(
            pmid, w2_l, px, px, SEQ, HIDDEN, FFN);
    }

    rmsnorm_kernel<<<SEQ, 256>>>(px, ph);
    gemm_hmma_kernel<0><<<dim3((VOCABSZ + 127) / 128, SEQ / 128), 256>>>(
        ph, lm, out, nullptr, SEQ, VOCABSZ, HIDDEN);
}

// round 6
// speedup vs baseline: 8.1474x; 1.0899x over previous
#include <cuda_runtime.h>
#include <cuda_bf16.h>
#include <math.h>
#include <stdint.h>

#define SEQ     2048
#define HIDDEN  1024
#define NH      16
#define HD      64
#define NL      8
#define VOCABSZ 50272
#define FFN     4096
#define EPSV    1e-5f

// weight element offsets in the packed split buffers
#define OFF_WQKV 0ULL
#define OFF_WO   25165824ULL
#define OFF_W1   33554432ULL
#define OFF_W2   67108864ULL
#define OFF_LM   100663296ULL
#define W_TOTAL  152141824ULL

// ---------------- scratch (device globals; no allocs allowed) ----------------
__device__ float g_x  [(size_t)SEQ * HIDDEN];
__device__ float g_qkv[(size_t)SEQ * 3 * HIDDEN];
__device__ float g_cos[(size_t)SEQ * (HD / 2)];
__device__ float g_sin[(size_t)SEQ * (HD / 2)];
__device__ __nv_bfloat16 g_wh[W_TOTAL];
__device__ __nv_bfloat16 g_wl[W_TOTAL];
__device__ __nv_bfloat16 g_hh[(size_t)SEQ * HIDDEN], g_hl[(size_t)SEQ * HIDDEN];
__device__ __nv_bfloat16 g_ah[(size_t)SEQ * HIDDEN], g_al[(size_t)SEQ * HIDDEN];
__device__ __nv_bfloat16 g_mh[(size_t)SEQ * FFN],    g_ml[(size_t)SEQ * FFN];

// ---------------- helpers ----------------
__device__ __forceinline__ uint32_t smem_u32(const void* p) {
    uint32_t a;
    asm("{ .reg .u64 t; cvta.to.shared.u64 t, %1; cvt.u32.u64 %0, t; }" : "=r"(a) : "l"(p));
    return a;
}
__device__ __forceinline__ float warpSum(float v) {
    #pragma unroll
    for (int o = 16; o; o >>= 1) v += __shfl_xor_sync(0xffffffffu, v, o);
    return v;
}
__device__ __forceinline__ float blockReduceSum(float v, float* red) {
    int lane = threadIdx.x & 31, w = threadIdx.x >> 5;
    v = warpSum(v);
    if (lane == 0) red[w] = v;
    __syncthreads();
    if (w == 0) {
        float r = (lane < (int)(blockDim.x >> 5)) ? red[lane] : 0.0f;
        r = warpSum(r);
        if (lane == 0) red[0] = r;
    }
    __syncthreads();
    float out = red[0];
    __syncthreads();
    return out;
}
__device__ __forceinline__ void mma_bf16(float* c, const uint32_t* a, const uint32_t* b) {
    asm volatile(
        "mma.sync.aligned.m16n8k16.row.col.f32.bf16.bf16.f32 "
        "{%0,%1,%2,%3}, {%4,%5,%6,%7}, {%8,%9}, {%0,%1,%2,%3};"
        : "+f"(c[0]), "+f"(c[1]), "+f"(c[2]), "+f"(c[3])
        : "r"(a[0]), "r"(a[1]), "r"(a[2]), "r"(a[3]), "r"(b[0]), "r"(b[1]));
}
__device__ __forceinline__ void ldmx4(uint32_t* d, uint32_t addr) {
    asm volatile("ldmatrix.sync.aligned.m8n8.x4.shared.b16 {%0,%1,%2,%3}, [%4];"
                 : "=r"(d[0]), "=r"(d[1]), "=r"(d[2]), "=r"(d[3]) : "r"(addr));
}
__device__ __forceinline__ void ldmx4t(uint32_t* d, uint32_t addr) {
    asm volatile("ldmatrix.sync.aligned.m8n8.x4.trans.shared.b16 {%0,%1,%2,%3}, [%4];"
                 : "=r"(d[0]), "=r"(d[1]), "=r"(d[2]), "=r"(d[3]) : "r"(addr));
}
__device__ __forceinline__ void split4(float4 f, uint2& h, uint2& l) {
    __nv_bfloat162 h0 = __floats2bfloat162_rn(f.x, f.y);
    __nv_bfloat162 h1 = __floats2bfloat162_rn(f.z, f.w);
    __nv_bfloat162 l0 = __floats2bfloat162_rn(f.x - __bfloat162float(h0.x),
                                              f.y - __bfloat162float(h0.y));
    __nv_bfloat162 l1 = __floats2bfloat162_rn(f.z - __bfloat162float(h1.x),
                                              f.w - __bfloat162float(h1.y));
    h.x = *(uint32_t*)&h0; h.y = *(uint32_t*)&h1;
    l.x = *(uint32_t*)&l0; l.y = *(uint32_t*)&l1;
}
__device__ __forceinline__ void cpa16(uint32_t s, const void* g, int srcsz) {
    asm volatile("cp.async.cg.shared.global [%0], [%1], 16, %2;"
                 :: "r"(s), "l"(g), "r"(srcsz) : "memory");
}
__device__ __forceinline__ void cpa_commit() {
    asm volatile("cp.async.commit_group;" ::: "memory");
}
__device__ __forceinline__ void cpa_wait0() {
    asm volatile("cp.async.wait_group 0;" ::: "memory");
}
__device__ __forceinline__ void cpa_wait1() {
    asm volatile("cp.async.wait_group 1;" ::: "memory");
}

// ---------------- weight split (fp32 -> bf16 hi/lo) ----------------
__global__ void wsplit_kernel(const float4* __restrict__ src, uint32_t* __restrict__ dh,
                              uint32_t* __restrict__ dl, size_t n4) {
    size_t i = (size_t)blockIdx.x * blockDim.x + threadIdx.x;
    if (i < n4) {
        uint2 h, l;
        split4(src[i], h, l);
        dh[2 * i] = h.x; dh[2 * i + 1] = h.y;
        dl[2 * i] = l.x; dl[2 * i + 1] = l.y;
    }
}

// ---------------- embedding + rmsnorm (fp32 residual base) ----------------
__global__ void embed_rmsnorm_kernel(const int* __restrict__ ids,
                                     const float* __restrict__ wte,
                                     float* __restrict__ out) {
    __shared__ float red[32];
    int t = blockIdx.x;
    const float* row = wte + (size_t)ids[t] * HIDDEN;
    float v[4]; float ss = 0.0f;
    #pragma unroll
    for (int i = 0; i < 4; i++) { v[i] = row[threadIdx.x + i * 256]; ss += v[i] * v[i]; }
    ss = blockReduceSum(ss, red);
    float sc = rsqrtf(ss * (1.0f / HIDDEN) + EPSV);
    #pragma unroll
    for (int i = 0; i < 4; i++)
        out[(size_t)t * HIDDEN + threadIdx.x + i * 256] = v[i] * sc;
}

// ---------------- rmsnorm: fp32 in -> bf16 hi/lo out ----------------
__global__ void rmsnorm_split_kernel(const float* __restrict__ in,
                                     __nv_bfloat16* __restrict__ oh,
                                     __nv_bfloat16* __restrict__ ol) {
    __shared__ float red[32];
    int t = blockIdx.x;
    const float* row = in + (size_t)t * HIDDEN;
    float v[4]; float ss = 0.0f;
    #pragma unroll
    for (int i = 0; i < 4; i++) {
        int idx = 2 * threadIdx.x + (i & 1) + (i >> 1) * 512;
        v[i] = row[idx];
        ss += v[i] * v[i];
    }
    ss = blockReduceSum(ss, red);
    float sc = rsqrtf(ss * (1.0f / HIDDEN) + EPSV);
    #pragma unroll
    for (int p = 0; p < 2; p++) {
        float a = v[2 * p] * sc, b = v[2 * p + 1] * sc;
        __nv_bfloat162 hh = __floats2bfloat162_rn(a, b);
        __nv_bfloat162 ll = __floats2bfloat162_rn(a - __bfloat162float(hh.x),
                                                  b - __bfloat162float(hh.y));
        size_t off = (size_t)t * HIDDEN + 2 * threadIdx.x + p * 512;
        *(uint32_t*)((char*)oh + off * 2) = *(uint32_t*)&hh;
        *(uint32_t*)((char*)ol + off * 2) = *(uint32_t*)&ll;
    }
}

// ---------------- rope tables ----------------
__global__ void rope_init_kernel(float* __restrict__ ctab, float* __restrict__ stab) {
    int t = blockIdx.x, i = threadIdx.x;
    float invf = (float)pow(10000.0, -(double)(2 * i) / (double)HD);
    float ang = (float)t * invf;
    float s, c;
    sincosf(ang, &s, &c);
    ctab[t * 32 + i] = c;
    stab[t * 32 + i] = s;
}

// ---------------- per-head rmsnorm + rope on q,k ----------------
__global__ void qknorm_rope_kernel(float* __restrict__ qkv,
                                   const float* __restrict__ ctab,
                                   const float* __restrict__ stab) {
    int t = blockIdx.x, h = blockIdx.y, w = blockIdx.z;
    float* p = qkv + (size_t)t * (3 * HIDDEN) + (size_t)w * HIDDEN + h * HD;
    int i = threadIdx.x;
    float x0 = p[2 * i], x1 = p[2 * i + 1];
    float ss = warpSum(x0 * x0 + x1 * x1);
    float sc = rsqrtf(ss * (1.0f / HD) + EPSV);
    x0 *= sc; x1 *= sc;
    float c = ctab[t * 32 + i], s = stab[t * 32 + i];
    p[2 * i]     = x1 * c - x0 * s;
    p[2 * i + 1] = x1 * s + x0 * c;
}

// ================= fused flash attention (bf16-split HMMA) =================
#define FRS       72
#define FT_BYTES  (64 * FRS * 2)
#define FLASH_SMEM (6 * FT_BYTES)

__global__ void __launch_bounds__(128, 2)
flash_attn_kernel(const float* __restrict__ qkv,
                  __nv_bfloat16* __restrict__ outh, __nv_bfloat16* __restrict__ outl) {
    extern __shared__ char fsm[];
    char* pQh = fsm;
    char* pQl = fsm + FT_BYTES;
    char* pKh = fsm + 2 * FT_BYTES;
    char* pKl = fsm + 3 * FT_BYTES;
    char* pVh = fsm + 4 * FT_BYTES;
    char* pVl = fsm + 5 * FT_BYTES;

    int tid = threadIdx.x, lane = tid & 31, wid = tid >> 5;
    int h = blockIdx.y;
    int qt = (int)gridDim.x - 1 - (int)blockIdx.x;
    int bm = qt * 64;

    int r = tid >> 1, c0 = (tid & 1) * 32;
    uint32_t soff = (uint32_t)((r * FRS + c0) * 2);

    uint32_t uQh = smem_u32(pQh), uQl = smem_u32(pQl);
    uint32_t uKh = smem_u32(pKh), uKl = smem_u32(pKl);
    uint32_t uVh = smem_u32(pVh), uVl = smem_u32(pVl);

    {
        const float* Qrow = qkv + (size_t)(bm + r) * (3 * HIDDEN) + h * HD + c0;
        #pragma unroll
        for (int g = 0; g < 8; g++) {
            uint2 hh, ll;
            split4(*(const float4*)(Qrow + g * 4), hh, ll);
            *(uint2*)(pQh + soff + g * 8) = hh;
            *(uint2*)(pQl + soff + g * 8) = ll;
        }
    }
    __syncthreads();

    uint32_t qh[4][4], ql[4][4];
    {
        uint32_t qoff = (uint32_t)(((wid * 16 + (lane & 15)) * FRS + ((lane >> 4) & 1) * 8) * 2);
        #pragma unroll
        for (int ks = 0; ks < 4; ks++) {
            ldmx4(qh[ks], uQh + qoff + ks * 32);
            ldmx4(ql[ks], uQl + qoff + ks * 32);
        }
    }

    float o[8][4] = {};
    float m[2] = {-INFINITY, -INFINITY};
    float l[2] = {0.0f, 0.0f};

    for (int jt = 0; jt <= qt; jt++) {
        __syncthreads();
        {
            const float* Krow = qkv + (size_t)(jt * 64 + r) * (3 * HIDDEN) + HIDDEN + h * HD + c0;
            const float* Vrow = Krow + HIDDEN;
            #pragma unroll
            for (int g = 0; g < 8; g++) {
                uint2 hh, ll;
                split4(*(const float4*)(Krow + g * 4), hh, ll);
                *(uint2*)(pKh + soff + g * 8) = hh;
                *(uint2*)(pKl + soff + g * 8) = ll;
                split4(*(const float4*)(Vrow + g * 4), hh, ll);
                *(uint2*)(pVh + soff + g * 8) = hh;
                *(uint2*)(pVl + soff + g * 8) = ll;
            }
        }
        __syncthreads();

        float s[8][4] = {};
        uint32_t bbase = (uint32_t)(((((lane >> 4) & 1) * 8 + (lane & 7)) * FRS
                                     + ((lane >> 3) & 1) * 8) * 2);
        #pragma unroll
        for (int ks = 0; ks < 4; ks++) {
            #pragma unroll
            for (int nb = 0; nb < 4; nb++) {
                uint32_t kh[4], kl[4];
                uint32_t bo = bbase + (uint32_t)(nb * 16 * FRS * 2) + (uint32_t)(ks * 32);
                ldmx4(kh, uKh + bo);
                ldmx4(kl, uKl + bo);
                mma_bf16(s[nb * 2],     qh[ks], kh + 0);
                mma_bf16(s[nb * 2 + 1], qh[ks], kh + 2);
                mma_bf16(s[nb * 2],     qh[ks], kl + 0);
                mma_bf16(s[nb * 2 + 1], qh[ks], kl + 2);
                mma_bf16(s[nb * 2],     ql[ks], kh + 0);
                mma_bf16(s[nb * 2 + 1], ql[ks], kh + 2);
            }
        }
        #pragma unroll
        for (int nt = 0; nt < 8; nt++)
            #pragma unroll
            for (int c = 0; c < 4; c++) s[nt][c] *= 0.125f;

        if (jt == qt) {
            int q0 = wid * 16 + (lane >> 2);
            int q1 = q0 + 8;
            #pragma unroll
            for (int nt = 0; nt < 8; nt++) {
                int j0 = nt * 8 + (lane & 3) * 2;
                if (j0     > q0) s[nt][0] = -INFINITY;
                if (j0 + 1 > q0) s[nt][1] = -INFINITY;
                if (j0     > q1) s[nt][2] = -INFINITY;
                if (j0 + 1 > q1) s[nt][3] = -INFINITY;
            }
        }

        #pragma unroll
        for (int hh = 0; hh < 2; hh++) {
            float rm = -INFINITY;
            #pragma unroll
            for (int nt = 0; nt < 8; nt++)
                rm = fmaxf(rm, fmaxf(s[nt][2 * hh], s[nt][2 * hh + 1]));
            rm = fmaxf(rm, __shfl_xor_sync(0xffffffffu, rm, 1));
            rm = fmaxf(rm, __shfl_xor_sync(0xffffffffu, rm, 2));
            float mnew = fmaxf(m[hh], rm);
            float corr = __expf(m[hh] - mnew);
            float rs = 0.0f;
            #pragma unroll
            for (int nt = 0; nt < 8; nt++) {
                float p0 = __expf(s[nt][2 * hh]     - mnew);
                float p1 = __expf(s[nt][2 * hh + 1] - mnew);
                s[nt][2 * hh] = p0; s[nt][2 * hh + 1] = p1;
                rs += p0 + p1;
            }
            rs += __shfl_xor_sync(0xffffffffu, rs, 1);
            rs += __shfl_xor_sync(0xffffffffu, rs, 2);
            l[hh] = l[hh] * corr + rs;
            m[hh] = mnew;
            #pragma unroll
            for (int dt = 0; dt < 8; dt++) {
                o[dt][2 * hh] *= corr; o[dt][2 * hh + 1] *= corr;
            }
        }

        #pragma unroll
        for (int jks = 0; jks < 4; jks++) {
            float* ce = s[2 * jks];
            float* co = s[2 * jks + 1];
            uint32_t pa[4], pb[4];
            {
                __nv_bfloat162 h0 = __floats2bfloat162_rn(ce[0], ce[1]);
                __nv_bfloat162 h1 = __floats2bfloat162_rn(ce[2], ce[3]);
                __nv_bfloat162 h2 = __floats2bfloat162_rn(co[0], co[1]);
                __nv_bfloat162 h3 = __floats2bfloat162_rn(co[2], co[3]);
                pa[0] = *(uint32_t*)&h0; pa[1] = *(uint32_t*)&h1;
                pa[2] = *(uint32_t*)&h2; pa[3] = *(uint32_t*)&h3;
                __nv_bfloat162 e0 = __floats2bfloat162_rn(ce[0] - __bfloat162float(h0.x),
                                                          ce[1] - __bfloat162float(h0.y));
                __nv_bfloat162 e1 = __floats2bfloat162_rn(ce[2] - __bfloat162float(h1.x),
                                                          ce[3] - __bfloat162float(h1.y));
                __nv_bfloat162 e2 = __floats2bfloat162_rn(co[0] - __bfloat162float(h2.x),
                                                          co[1] - __bfloat162float(h2.y));
                __nv_bfloat162 e3 = __floats2bfloat162_rn(co[2] - __bfloat162float(h3.x),
                                                          co[3] - __bfloat162float(h3.y));
                pb[0] = *(uint32_t*)&e0; pb[1] = *(uint32_t*)&e1;
                pb[2] = *(uint32_t*)&e2; pb[3] = *(uint32_t*)&e3;
            }
            uint32_t vbase = (uint32_t)(((jks * 16 + (lane & 15)) * FRS
                                         + ((lane >> 4) & 1) * 8) * 2);
            #pragma unroll
            for (int db = 0; db < 4; db++) {
                uint32_t vh[4], vl[4];
                uint32_t vo = vbase + (uint32_t)(db * 32);
                ldmx4t(vh, uVh + vo);
                ldmx4t(vl, uVl + vo);
                mma_bf16(o[db * 2],     pa, vh + 0);
                mma_bf16(o[db * 2 + 1], pa, vh + 2);
                mma_bf16(o[db * 2],     pa, vl + 0);
                mma_bf16(o[db * 2 + 1], pa, vl + 2);
                mma_bf16(o[db * 2],     pb, vh + 0);
                mma_bf16(o[db * 2 + 1], pb, vh + 2);
            }
        }
    }

    // ---- finalize: write bf16 hi/lo ----
    float inv0 = 1.0f / l[0], inv1 = 1.0f / l[1];
    int row0 = bm + wid * 16 + (lane >> 2);
    #pragma unroll
    for (int dt = 0; dt < 8; dt++) {
        int col = h * HD + dt * 8 + (lane & 3) * 2;
        float a0 = o[dt][0] * inv0, b0 = o[dt][1] * inv0;
        float a1 = o[dt][2] * inv1, b1 = o[dt][3] * inv1;
        __nv_bfloat162 hh0 = __floats2bfloat162_rn(a0, b0);
        __nv_bfloat162 ll0 = __floats2bfloat162_rn(a0 - __bfloat162float(hh0.x),
                                                   b0 - __bfloat162float(hh0.y));
        __nv_bfloat162 hh1 = __floats2bfloat162_rn(a1, b1);
        __nv_bfloat162 ll1 = __floats2bfloat162_rn(a1 - __bfloat162float(hh1.x),
                                                   b1 - __bfloat162float(hh1.y));
        size_t off0 = (size_t)row0 * HIDDEN + col;
        size_t off1 = (size_t)(row0 + 8) * HIDDEN + col;
        *(uint32_t*)((char*)outh + off0 * 2) = *(uint32_t*)&hh0;
        *(uint32_t*)((char*)outl + off0 * 2) = *(uint32_t*)&ll0;
        *(uint32_t*)((char*)outh + off1 * 2) = *(uint32_t*)&hh1;
        *(uint32_t*)((char*)outl + off1 * 2) = *(uint32_t*)&ll1;
    }
}

// ================= bf16-split GEMM with cp.async double buffering =================
// C[M,N] = A[M,K] @ B[N,K]^T from pre-split bf16 hi/lo operands.
// EPI 0: C = AB   EPI 1: C = R + AB   EPI 2: Oh/Ol = split(relu(AB)^2)
#define RS 40
#define GT_BYTES 10240                 // 128 rows x 40 cols x 2B
#define GSTAGE   (4 * GT_BYTES)        // Ah, Al, Bh, Bl
#define GEMM_SMEM (2 * GSTAGE)         // 81920

template <int EPI>
__global__ void __launch_bounds__(256, 2)
gemm_bf16_kernel(const __nv_bfloat16* __restrict__ Ah, const __nv_bfloat16* __restrict__ Al,
                 const __nv_bfloat16* __restrict__ Bh, const __nv_bfloat16* __restrict__ Bl,
                 float* __restrict__ C, const float* __restrict__ R,
                 __nv_bfloat16* __restrict__ Oh, __nv_bfloat16* __restrict__ Ol,
                 int M, int N, int K) {
    extern __shared__ char gsm[];
    int tid = threadIdx.x, lane = tid & 31, wid = tid >> 5;
    int wm = wid >> 2, wn = wid & 3;
    int bm = blockIdx.y * 128, bn = blockIdx.x * 128;
    int row = tid >> 1, half = tid & 1;
    int brow = bn + row;
    bool bok = brow < N;
    int browc = bok ? brow : (N - 1);

    uint32_t sb = smem_u32(gsm);
    uint32_t so = (uint32_t)(row * 80 + half * 32);
    const char* gAh = (const char*)(Ah + (size_t)(bm + row) * K + half * 16);
    const char* gAl = (const char*)(Al + (size_t)(bm + row) * K + half * 16);
    const char* gBh = (const char*)(Bh + (size_t)browc * K + half * 16);
    const char* gBl = (const char*)(Bl + (size_t)browc * K + half * 16);
    int bsz = bok ? 16 : 0;

    uint32_t aoff = (uint32_t)(((wm * 64 + (lane & 15)) * RS + ((lane >> 4) & 1) * 8) * 2);
    uint32_t boff = (uint32_t)(((wn * 32 + ((lane >> 4) & 1) * 8 + (lane & 7)) * RS
                                + ((lane >> 3) & 1) * 8) * 2);

    float acc[4][4][4] = {};
    int nCh = K >> 5;

    // issue chunk 0
    {
        uint32_t s0 = sb;
        cpa16(s0 + so,                    gAh, 16);
        cpa16(s0 + so + 16,               gAh + 16, 16);
        cpa16(s0 + GT_BYTES + so,         gAl, 16);
        cpa16(s0 + GT_BYTES + so + 16,    gAl + 16, 16);
        cpa16(s0 + 2 * GT_BYTES + so,     gBh, bsz);
        cpa16(s0 + 2 * GT_BYTES + so + 16, gBh + 16, bsz);
        cpa16(s0 + 3 * GT_BYTES + so,     gBl, bsz);
        cpa16(s0 + 3 * GT_BYTES + so + 16, gBl + 16, bsz);
        cpa_commit();
    }

    for (int s = 0; s < nCh; s++) {
        if (s + 1 < nCh) {
            uint32_t s1 = sb + ((s + 1) & 1) * GSTAGE;
            int kb = (s + 1) * 64;   // byte offset for 32 bf16
            cpa16(s1 + so,                     gAh + kb, 16);
            cpa16(s1 + so + 16,                gAh + kb + 16, 16);
            cpa16(s1 + GT_BYTES + so,          gAl + kb, 16);
            cpa16(s1 + GT_BYTES + so + 16,     gAl + kb + 16, 16);
            cpa16(s1 + 2 * GT_BYTES + so,      gBh + kb, bsz);
            cpa16(s1 + 2 * GT_BYTES + so + 16, gBh + kb + 16, bsz);
            cpa16(s1 + 3 * GT_BYTES + so,      gBl + kb, bsz);
            cpa16(s1 + 3 * GT_BYTES + so + 16, gBl + kb + 16, bsz);
            cpa_commit();
            cpa_wait1();
        } else {
            cpa_wait0();
        }
        __syncthreads();

        uint32_t st = sb + (s & 1) * GSTAGE;
        uint32_t uAh = st, uAl = st + GT_BYTES, uBh = st + 2 * GT_BYTES, uBl = st + 3 * GT_BYTES;
        #pragma unroll
        for (int ks = 0; ks < 2; ks++) {
            uint32_t k2 = (uint32_t)(ks * 32);
            uint32_t aH[4][4], aL[4][4], bH[2][4], bL[2][4];
            #pragma unroll
            for (int mt = 0; mt < 4; mt++) ldmx4(aH[mt], uAh + aoff + mt * (16 * RS * 2) + k2);
            #pragma unroll
            for (int np = 0; np < 2; np++) ldmx4(bH[np], uBh + boff + np * (16 * RS * 2) + k2);
            #pragma unroll
            for (int mt = 0; mt < 4; mt++)
                #pragma unroll
                for (int nt = 0; nt < 4; nt++)
                    mma_bf16(acc[mt][nt], aH[mt], &bH[nt >> 1][(nt & 1) * 2]);
            #pragma unroll
            for (int np = 0; np < 2; np++) ldmx4(bL[np], uBl + boff + np * (16 * RS * 2) + k2);
            #pragma unroll
            for (int mt = 0; mt < 4; mt++)
                #pragma unroll
                for (int nt = 0; nt < 4; nt++)
                    mma_bf16(acc[mt][nt], aH[mt], &bL[nt >> 1][(nt & 1) * 2]);
            #pragma unroll
            for (int mt = 0; mt < 4; mt++) ldmx4(aL[mt], uAl + aoff + mt * (16 * RS * 2) + k2);
            #pragma unroll
            for (int mt = 0; mt < 4; mt++)
                #pragma unroll
                for (int nt = 0; nt < 4; nt++)
                    mma_bf16(acc[mt][nt], aL[mt], &bH[nt >> 1][(nt & 1) * 2]);
        }
        __syncthreads();
    }

    #pragma unroll
    for (int mt = 0; mt < 4; mt++) {
        int rw = bm + wm * 64 + mt * 16 + (lane >> 2);
        #pragma unroll
        for (int nt = 0; nt < 4; nt++) {
            int col = bn + wn * 32 + nt * 8 + (lane & 3) * 2;
            if (col < N) {
                float* c = acc[mt][nt];
                float v0 = c[0], v1 = c[1], v2 = c[2], v3 = c[3];
                if (EPI == 1) {
                    float2 r0 = *(const float2*)(R + (size_t)rw * N + col);
                    float2 r1 = *(const float2*)(R + (size_t)(rw + 8) * N + col);
                    v0 += r0.x; v1 += r0.y; v2 += r1.x; v3 += r1.y;
                }
                if (EPI == 2) {
                    v0 = fmaxf(v0, 0.f); v0 *= v0;
                    v1 = fmaxf(v1, 0.f); v1 *= v1;
                    v2 = fmaxf(v2, 0.f); v2 *= v2;
                    v3 = fmaxf(v3, 0.f); v3 *= v3;
                    __nv_bfloat162 hh0 = __floats2bfloat162_rn(v0, v1);
                    __nv_bfloat162 ll0 = __floats2bfloat162_rn(v0 - __bfloat162float(hh0.x),
                                                               v1 - __bfloat162float(hh0.y));
                    __nv_bfloat162 hh1 = __floats2bfloat162_rn(v2, v3);
                    __nv_bfloat162 ll1 = __floats2bfloat162_rn(v2 - __bfloat162float(hh1.x),
                                                               v3 - __bfloat162float(hh1.y));
                    size_t o0 = (size_t)rw * N + col;
                    size_t o1 = (size_t)(rw + 8) * N + col;
                    *(uint32_t*)((char*)Oh + o0 * 2) = *(uint32_t*)&hh0;
                    *(uint32_t*)((char*)Ol + o0 * 2) = *(uint32_t*)&ll0;
                    *(uint32_t*)((char*)Oh + o1 * 2) = *(uint32_t*)&hh1;
                    *(uint32_t*)((char*)Ol + o1 * 2) = *(uint32_t*)&ll1;
                } else {
                    *(float2*)(C + (size_t)rw * N + col) = make_float2(v0, v1);
                    *(float2*)(C + (size_t)(rw + 8) * N + col) = make_float2(v2, v3);
                }
            }
        }
    }
}

// ---------------- host launcher ----------------
extern "C" void kernel_launch(void* const* d_in, const int* in_sizes, int n_in,
                              void* d_out, int out_size) {
    const int*   ids  = (const int*)d_in[0];
    const float* wte  = (const float*)d_in[1];
    const float* wqkv = (const float*)d_in[2];
    const float* wo   = (const float*)d_in[3];
    const float* w1   = (const float*)d_in[4];
    const float* w2   = (const float*)d_in[5];
    const float* lm   = (const float*)d_in[6];
    float* out = (float*)d_out;

    float *px, *pqkv, *pcos, *psin;
    __nv_bfloat16 *pwh, *pwl, *phh, *phl, *pah, *pal, *pmh, *pml;
    cudaGetSymbolAddress((void**)&px,   g_x);
    cudaGetSymbolAddress((void**)&pqkv, g_qkv);
    cudaGetSymbolAddress((void**)&pcos, g_cos);
    cudaGetSymbolAddress((void**)&psin, g_sin);
    cudaGetSymbolAddress((void**)&pwh,  g_wh);
    cudaGetSymbolAddress((void**)&pwl,  g_wl);
    cudaGetSymbolAddress((void**)&phh,  g_hh);
    cudaGetSymbolAddress((void**)&phl,  g_hl);
    cudaGetSymbolAddress((void**)&pah,  g_ah);
    cudaGetSymbolAddress((void**)&pal,  g_al);
    cudaGetSymbolAddress((void**)&pmh,  g_mh);
    cudaGetSymbolAddress((void**)&pml,  g_ml);

    cudaFuncSetAttribute(flash_attn_kernel,
                         cudaFuncAttributeMaxDynamicSharedMemorySize, FLASH_SMEM);
    cudaFuncSetAttribute(gemm_bf16_kernel<0>,
                         cudaFuncAttributeMaxDynamicSharedMemorySize, GEMM_SMEM);
    cudaFuncSetAttribute(gemm_bf16_kernel<1>,
                         cudaFuncAttributeMaxDynamicSharedMemorySize, GEMM_SMEM);
    cudaFuncSetAttribute(gemm_bf16_kernel<2>,
                         cudaFuncAttributeMaxDynamicSharedMemorySize, GEMM_SMEM);

    // ---- weight pre-split ----
    {
        struct { const float* s; size_t off, n; } ws[5] = {
            {wqkv, OFF_WQKV, 25165824ULL},
            {wo,   OFF_WO,    8388608ULL},
            {w1,   OFF_W1,   33554432ULL},
            {w2,   OFF_W2,   33554432ULL},
            {lm,   OFF_LM,   51478528ULL},
        };
        for (int i = 0; i < 5; i++) {
            size_t n4 = ws[i].n / 4;
            wsplit_kernel<<<(unsigned)((n4 + 255) / 256), 256>>>(
                (const float4*)ws[i].s, (uint32_t*)(pwh + ws[i].off),
                (uint32_t*)(pwl + ws[i].off), n4);
        }
    }

    rope_init_kernel<<<SEQ, 32>>>(pcos, psin);
    embed_rmsnorm_kernel<<<SEQ, 256>>>(ids, wte, px);

    for (int l = 0; l < NL; l++) {
        __nv_bfloat16* wqkv_h = pwh + OFF_WQKV + (size_t)l * 3145728;
        __nv_bfloat16* wqkv_l2 = pwl + OFF_WQKV + (size_t)l * 3145728;
        __nv_bfloat16* wo_h = pwh + OFF_WO + (size_t)l * 1048576;
        __nv_bfloat16* wo_l2 = pwl + OFF_WO + (size_t)l * 1048576;
        __nv_bfloat16* w1_h = pwh + OFF_W1 + (size_t)l * 4194304;
        __nv_bfloat16* w1_l2 = pwl + OFF_W1 + (size_t)l * 4194304;
        __nv_bfloat16* w2_h = pwh + OFF_W2 + (size_t)l * 4194304;
        __nv_bfloat16* w2_l2 = pwl + OFF_W2 + (size_t)l * 4194304;

        rmsnorm_split_kernel<<<SEQ, 256>>>(px, phh, phl);
        gemm_bf16_kernel<0><<<dim3(24, 16), 256, GEMM_SMEM>>>(
            phh, phl, wqkv_h, wqkv_l2, pqkv, nullptr, nullptr, nullptr,
            SEQ, 3 * HIDDEN, HIDDEN);
        qknorm_rope_kernel<<<dim3(SEQ, NH, 2), 32>>>(pqkv, pcos, psin);
        flash_attn_kernel<<<dim3(SEQ / 64, NH), 128, FLASH_SMEM>>>(pqkv, pah, pal);
        gemm_bf16_kernel<1><<<dim3(8, 16), 256, GEMM_SMEM>>>(
            pah, pal, wo_h, wo_l2, px, px, nullptr, nullptr,
            SEQ, HIDDEN, HIDDEN);

        rmsnorm_split_kernel<<<SEQ, 256>>>(px, phh, phl);
        gemm_bf16_kernel<2><<<dim3(32, 16), 256, GEMM_SMEM>>>(
            phh, phl, w1_h, w1_l2, nullptr, nullptr, pmh, pml,
            SEQ, FFN, HIDDEN);
        gemm_bf16_kernel<1><<<dim3(8, 16), 256, GEMM_SMEM>>>(
            pmh, pml, w2_h, w2_l2, px, px, nullptr, nullptr,
            SEQ, HIDDEN, FFN);
    }

    rmsnorm_split_kernel<<<SEQ, 256>>>(px, phh, phl);
    gemm_bf16_kernel<0><<<dim3((VOCABSZ + 127) / 128, 16), 256, GEMM_SMEM>>>(
        phh, phl, pwh + OFF_LM, pwl + OFF_LM, out, nullptr, nullptr, nullptr,
        SEQ, VOCABSZ, HIDDEN);
}

// round 7
// speedup vs baseline: 8.5509x; 1.0495x over previous
#include <cuda_runtime.h>
#include <cuda_bf16.h>
#include <math.h>
#include <stdint.h>

#define SEQ     2048
#define HIDDEN  1024
#define NH      16
#define HD      64
#define NL      8
#define VOCABSZ 50272
#define FFN     4096
#define EPSV    1e-5f

#define OFF_WQKV 0ULL
#define OFF_WO   25165824ULL
#define OFF_W1   33554432ULL
#define OFF_W2   67108864ULL
#define OFF_LM   100663296ULL
#define W_TOTAL  152141824ULL

// ---------------- scratch ----------------
__device__ float g_x  [(size_t)SEQ * HIDDEN];
__device__ float g_qkv[(size_t)SEQ * 3 * HIDDEN];
__device__ float g_cos[(size_t)SEQ * (HD / 2)];
__device__ float g_sin[(size_t)SEQ * (HD / 2)];
__device__ __nv_bfloat16 g_wh[W_TOTAL];
__device__ __nv_bfloat16 g_wl[W_TOTAL];
__device__ __nv_bfloat16 g_sh[(size_t)SEQ * 3 * HIDDEN], g_sl[(size_t)SEQ * 3 * HIDDEN];
__device__ __nv_bfloat16 g_hh[(size_t)SEQ * HIDDEN], g_hl[(size_t)SEQ * HIDDEN];
__device__ __nv_bfloat16 g_ah[(size_t)SEQ * HIDDEN], g_al[(size_t)SEQ * HIDDEN];
__device__ __nv_bfloat16 g_mh[(size_t)SEQ * FFN],    g_ml[(size_t)SEQ * FFN];

// ---------------- helpers ----------------
__device__ __forceinline__ uint32_t smem_u32(const void* p) {
    uint32_t a;
    asm("{ .reg .u64 t; cvta.to.shared.u64 t, %1; cvt.u32.u64 %0, t; }" : "=r"(a) : "l"(p));
    return a;
}
__device__ __forceinline__ float warpSum(float v) {
    #pragma unroll
    for (int o = 16; o; o >>= 1) v += __shfl_xor_sync(0xffffffffu, v, o);
    return v;
}
__device__ __forceinline__ float blockReduceSum(float v, float* red) {
    int lane = threadIdx.x & 31, w = threadIdx.x >> 5;
    v = warpSum(v);
    if (lane == 0) red[w] = v;
    __syncthreads();
    if (w == 0) {
        float r = (lane < (int)(blockDim.x >> 5)) ? red[lane] : 0.0f;
        r = warpSum(r);
        if (lane == 0) red[0] = r;
    }
    __syncthreads();
    float out = red[0];
    __syncthreads();
    return out;
}
__device__ __forceinline__ void mma_bf16(float* c, const uint32_t* a, const uint32_t* b) {
    asm volatile(
        "mma.sync.aligned.m16n8k16.row.col.f32.bf16.bf16.f32 "
        "{%0,%1,%2,%3}, {%4,%5,%6,%7}, {%8,%9}, {%0,%1,%2,%3};"
        : "+f"(c[0]), "+f"(c[1]), "+f"(c[2]), "+f"(c[3])
        : "r"(a[0]), "r"(a[1]), "r"(a[2]), "r"(a[3]), "r"(b[0]), "r"(b[1]));
}
__device__ __forceinline__ void ldmx4(uint32_t* d, uint32_t addr) {
    asm volatile("ldmatrix.sync.aligned.m8n8.x4.shared.b16 {%0,%1,%2,%3}, [%4];"
                 : "=r"(d[0]), "=r"(d[1]), "=r"(d[2]), "=r"(d[3]) : "r"(addr));
}
__device__ __forceinline__ void ldmx4t(uint32_t* d, uint32_t addr) {
    asm volatile("ldmatrix.sync.aligned.m8n8.x4.trans.shared.b16 {%0,%1,%2,%3}, [%4];"
                 : "=r"(d[0]), "=r"(d[1]), "=r"(d[2]), "=r"(d[3]) : "r"(addr));
}
__device__ __forceinline__ void split4(float4 f, uint2& h, uint2& l) {
    __nv_bfloat162 h0 = __floats2bfloat162_rn(f.x, f.y);
    __nv_bfloat162 h1 = __floats2bfloat162_rn(f.z, f.w);
    __nv_bfloat162 l0 = __floats2bfloat162_rn(f.x - __bfloat162float(h0.x),
                                              f.y - __bfloat162float(h0.y));
    __nv_bfloat162 l1 = __floats2bfloat162_rn(f.z - __bfloat162float(h1.x),
                                              f.w - __bfloat162float(h1.y));
    h.x = *(uint32_t*)&h0; h.y = *(uint32_t*)&h1;
    l.x = *(uint32_t*)&l0; l.y = *(uint32_t*)&l1;
}
__device__ __forceinline__ void cpa16(uint32_t s, const void* g, int srcsz) {
    asm volatile("cp.async.cg.shared.global [%0], [%1], 16, %2;"
                 :: "r"(s), "l"(g), "r"(srcsz) : "memory");
}
__device__ __forceinline__ void cpa_commit() {
    asm volatile("cp.async.commit_group;" ::: "memory");
}
__device__ __forceinline__ void cpa_wait0() {
    asm volatile("cp.async.wait_group 0;" ::: "memory");
}

// ---------------- weight split ----------------
__global__ void wsplit_kernel(const float4* __restrict__ src, uint32_t* __restrict__ dh,
                              uint32_t* __restrict__ dl, size_t n4) {
    size_t i = (size_t)blockIdx.x * blockDim.x + threadIdx.x;
    if (i < n4) {
        uint2 h, l;
        split4(src[i], h, l);
        dh[2 * i] = h.x; dh[2 * i + 1] = h.y;
        dl[2 * i] = l.x; dl[2 * i + 1] = l.y;
    }
}

// ---------------- embedding + rmsnorm ----------------
__global__ void embed_rmsnorm_kernel(const int* __restrict__ ids,
                                     const float* __restrict__ wte,
                                     float* __restrict__ out) {
    __shared__ float red[32];
    int t = blockIdx.x;
    const float* row = wte + (size_t)ids[t] * HIDDEN;
    float v[4]; float ss = 0.0f;
    #pragma unroll
    for (int i = 0; i < 4; i++) { v[i] = row[threadIdx.x + i * 256]; ss += v[i] * v[i]; }
    ss = blockReduceSum(ss, red);
    float sc = rsqrtf(ss * (1.0f / HIDDEN) + EPSV);
    #pragma unroll
    for (int i = 0; i < 4; i++)
        out[(size_t)t * HIDDEN + threadIdx.x + i * 256] = v[i] * sc;
}

// ---------------- rmsnorm: fp32 in -> bf16 hi/lo ----------------
__global__ void rmsnorm_split_kernel(const float* __restrict__ in,
                                     __nv_bfloat16* __restrict__ oh,
                                     __nv_bfloat16* __restrict__ ol) {
    __shared__ float red[32];
    int t = blockIdx.x;
    const float* row = in + (size_t)t * HIDDEN;
    float v[4]; float ss = 0.0f;
    #pragma unroll
    for (int i = 0; i < 4; i++) {
        int idx = 2 * threadIdx.x + (i & 1) + (i >> 1) * 512;
        v[i] = row[idx];
        ss += v[i] * v[i];
    }
    ss = blockReduceSum(ss, red);
    float sc = rsqrtf(ss * (1.0f / HIDDEN) + EPSV);
    #pragma unroll
    for (int p = 0; p < 2; p++) {
        float a = v[2 * p] * sc, b = v[2 * p + 1] * sc;
        __nv_bfloat162 hh = __floats2bfloat162_rn(a, b);
        __nv_bfloat162 ll = __floats2bfloat162_rn(a - __bfloat162float(hh.x),
                                                  b - __bfloat162float(hh.y));
        size_t off = (size_t)t * HIDDEN + 2 * threadIdx.x + p * 512;
        *(uint32_t*)((char*)oh + off * 2) = *(uint32_t*)&hh;
        *(uint32_t*)((char*)ol + off * 2) = *(uint32_t*)&ll;
    }
}

// ---------------- rope tables ----------------
__global__ void rope_init_kernel(float* __restrict__ ctab, float* __restrict__ stab) {
    int t = blockIdx.x, i = threadIdx.x;
    float invf = (float)pow(10000.0, -(double)(2 * i) / (double)HD);
    float ang = (float)t * invf;
    float s, c;
    sincosf(ang, &s, &c);
    ctab[t * 32 + i] = c;
    stab[t * 32 + i] = s;
}

// ---------------- per-head rmsnorm + rope on q,k ; split all of q,k,v ----------------
// grid (SEQ, NH, 3), 32 threads. w=0,1: norm+rope+split. w=2: split V only.
__global__ void qknorm_rope_split_kernel(const float* __restrict__ qkv,
                                         const float* __restrict__ ctab,
                                         const float* __restrict__ stab,
                                         __nv_bfloat16* __restrict__ oh,
                                         __nv_bfloat16* __restrict__ ol) {
    int t = blockIdx.x, h = blockIdx.y, w = blockIdx.z;
    size_t base = (size_t)t * (3 * HIDDEN) + (size_t)w * HIDDEN + h * HD;
    const float* p = qkv + base;
    int i = threadIdx.x;
    float x0 = p[2 * i], x1 = p[2 * i + 1];
    float y0, y1;
    if (w < 2) {
        float ss = warpSum(x0 * x0 + x1 * x1);
        float sc = rsqrtf(ss * (1.0f / HD) + EPSV);
        x0 *= sc; x1 *= sc;
        float c = ctab[t * 32 + i], s = stab[t * 32 + i];
        y0 = x1 * c - x0 * s;
        y1 = x1 * s + x0 * c;
    } else {
        y0 = x0; y1 = x1;
    }
    __nv_bfloat162 hh = __floats2bfloat162_rn(y0, y1);
    __nv_bfloat162 ll = __floats2bfloat162_rn(y0 - __bfloat162float(hh.x),
                                              y1 - __bfloat162float(hh.y));
    *(uint32_t*)((char*)oh + (base + 2 * i) * 2) = *(uint32_t*)&hh;
    *(uint32_t*)((char*)ol + (base + 2 * i) * 2) = *(uint32_t*)&ll;
}

// ================= fused flash attention (pre-split bf16, cp.async pipelined) =================
#define FRS       72
#define FT_BYTES  (64 * FRS * 2)              // 9216
#define KV_STAGE  (4 * FT_BYTES)              // 36864
#define FLASH_SMEM (2 * FT_BYTES + 2 * KV_STAGE)   // 92160

__global__ void __launch_bounds__(128, 2)
flash_attn_kernel(const __nv_bfloat16* __restrict__ qh_g,
                  const __nv_bfloat16* __restrict__ ql_g,
                  __nv_bfloat16* __restrict__ outh, __nv_bfloat16* __restrict__ outl) {
    extern __shared__ char fsm[];
    uint32_t sb = smem_u32(fsm);
    uint32_t uQh = sb, uQl = sb + FT_BYTES;

    int tid = threadIdx.x, lane = tid & 31, wid = tid >> 5;
    int h = blockIdx.y;
    int qt = (int)gridDim.x - 1 - (int)blockIdx.x;
    int bm = qt * 64;

    int r = tid >> 1, c0 = (tid & 1) * 32;
    uint32_t soff = (uint32_t)(r * (FRS * 2) + c0 * 2);

    // ---- issue Q + KV(0) loads as one group ----
    {
        const char* gQh = (const char*)(qh_g + (size_t)(bm + r) * (3 * HIDDEN) + h * HD + c0);
        const char* gQl = (const char*)(ql_g + (size_t)(bm + r) * (3 * HIDDEN) + h * HD + c0);
        #pragma unroll
        for (int g = 0; g < 4; g++) {
            cpa16(uQh + soff + g * 16, gQh + g * 16, 16);
            cpa16(uQl + soff + g * 16, gQl + g * 16, 16);
        }
        const char* gKh = (const char*)(qh_g + (size_t)r * (3 * HIDDEN) + HIDDEN + h * HD + c0);
        const char* gKl = (const char*)(ql_g + (size_t)r * (3 * HIDDEN) + HIDDEN + h * HD + c0);
        uint32_t st = sb + 2 * FT_BYTES;
        #pragma unroll
        for (int g = 0; g < 4; g++) {
            cpa16(st + soff + g * 16,                gKh + g * 16, 16);
            cpa16(st + FT_BYTES + soff + g * 16,     gKl + g * 16, 16);
            cpa16(st + 2 * FT_BYTES + soff + g * 16, gKh + HIDDEN * 2 + g * 16, 16);
            cpa16(st + 3 * FT_BYTES + soff + g * 16, gKl + HIDDEN * 2 + g * 16, 16);
        }
        cpa_commit();
    }

    uint32_t qh[4][4], ql[4][4];
    float o[8][4] = {};
    float m[2] = {-INFINITY, -INFINITY};
    float l[2] = {0.0f, 0.0f};

    for (int jt = 0; jt <= qt; jt++) {
        cpa_wait0();
        __syncthreads();

        if (jt == 0) {
            uint32_t qoff = (uint32_t)(((wid * 16 + (lane & 15)) * FRS + ((lane >> 4) & 1) * 8) * 2);
            #pragma unroll
            for (int ks = 0; ks < 4; ks++) {
                ldmx4(qh[ks], uQh + qoff + ks * 32);
                ldmx4(ql[ks], uQl + qoff + ks * 32);
            }
        }
        if (jt + 1 <= qt) {
            const char* gKh = (const char*)(qh_g + (size_t)((jt + 1) * 64 + r) * (3 * HIDDEN) + HIDDEN + h * HD + c0);
            const char* gKl = (const char*)(ql_g + (size_t)((jt + 1) * 64 + r) * (3 * HIDDEN) + HIDDEN + h * HD + c0);
            uint32_t st = sb + 2 * FT_BYTES + (uint32_t)((jt + 1) & 1) * KV_STAGE;
            #pragma unroll
            for (int g = 0; g < 4; g++) {
                cpa16(st + soff + g * 16,                gKh + g * 16, 16);
                cpa16(st + FT_BYTES + soff + g * 16,     gKl + g * 16, 16);
                cpa16(st + 2 * FT_BYTES + soff + g * 16, gKh + HIDDEN * 2 + g * 16, 16);
                cpa16(st + 3 * FT_BYTES + soff + g * 16, gKl + HIDDEN * 2 + g * 16, 16);
            }
            cpa_commit();
        }

        uint32_t stg = sb + 2 * FT_BYTES + (uint32_t)(jt & 1) * KV_STAGE;
        uint32_t uKh = stg, uKl = stg + FT_BYTES, uVh = stg + 2 * FT_BYTES, uVl = stg + 3 * FT_BYTES;

        // ---- scores ----
        float s[8][4] = {};
        uint32_t bbase = (uint32_t)(((((lane >> 4) & 1) * 8 + (lane & 7)) * FRS
                                     + ((lane >> 3) & 1) * 8) * 2);
        #pragma unroll
        for (int ks = 0; ks < 4; ks++) {
            #pragma unroll
            for (int nb = 0; nb < 4; nb++) {
                uint32_t kh[4], kl[4];
                uint32_t bo = bbase + (uint32_t)(nb * 16 * FRS * 2) + (uint32_t)(ks * 32);
                ldmx4(kh, uKh + bo);
                ldmx4(kl, uKl + bo);
                mma_bf16(s[nb * 2],     qh[ks], kh + 0);
                mma_bf16(s[nb * 2 + 1], qh[ks], kh + 2);
                mma_bf16(s[nb * 2],     qh[ks], kl + 0);
                mma_bf16(s[nb * 2 + 1], qh[ks], kl + 2);
                mma_bf16(s[nb * 2],     ql[ks], kh + 0);
                mma_bf16(s[nb * 2 + 1], ql[ks], kh + 2);
            }
        }
        #pragma unroll
        for (int nt = 0; nt < 8; nt++)
            #pragma unroll
            for (int c = 0; c < 4; c++) s[nt][c] *= 0.125f;

        if (jt == qt) {
            int q0 = wid * 16 + (lane >> 2);
            int q1 = q0 + 8;
            #pragma unroll
            for (int nt = 0; nt < 8; nt++) {
                int j0 = nt * 8 + (lane & 3) * 2;
                if (j0     > q0) s[nt][0] = -INFINITY;
                if (j0 + 1 > q0) s[nt][1] = -INFINITY;
                if (j0     > q1) s[nt][2] = -INFINITY;
                if (j0 + 1 > q1) s[nt][3] = -INFINITY;
            }
        }

        #pragma unroll
        for (int hh = 0; hh < 2; hh++) {
            float rm = -INFINITY;
            #pragma unroll
            for (int nt = 0; nt < 8; nt++)
                rm = fmaxf(rm, fmaxf(s[nt][2 * hh], s[nt][2 * hh + 1]));
            rm = fmaxf(rm, __shfl_xor_sync(0xffffffffu, rm, 1));
            rm = fmaxf(rm, __shfl_xor_sync(0xffffffffu, rm, 2));
            float mnew = fmaxf(m[hh], rm);
            float corr = __expf(m[hh] - mnew);
            float rs = 0.0f;
            #pragma unroll
            for (int nt = 0; nt < 8; nt++) {
                float p0 = __expf(s[nt][2 * hh]     - mnew);
                float p1 = __expf(s[nt][2 * hh + 1] - mnew);
                s[nt][2 * hh] = p0; s[nt][2 * hh + 1] = p1;
                rs += p0 + p1;
            }
            rs += __shfl_xor_sync(0xffffffffu, rs, 1);
            rs += __shfl_xor_sync(0xffffffffu, rs, 2);
            l[hh] = l[hh] * corr + rs;
            m[hh] = mnew;
            #pragma unroll
            for (int dt = 0; dt < 8; dt++) {
                o[dt][2 * hh] *= corr; o[dt][2 * hh + 1] *= corr;
            }
        }

        #pragma unroll
        for (int jks = 0; jks < 4; jks++) {
            float* ce = s[2 * jks];
            float* co = s[2 * jks + 1];
            uint32_t pa[4], pb[4];
            {
                __nv_bfloat162 h0 = __floats2bfloat162_rn(ce[0], ce[1]);
                __nv_bfloat162 h1 = __floats2bfloat162_rn(ce[2], ce[3]);
                __nv_bfloat162 h2 = __floats2bfloat162_rn(co[0], co[1]);
                __nv_bfloat162 h3 = __floats2bfloat162_rn(co[2], co[3]);
                pa[0] = *(uint32_t*)&h0; pa[1] = *(uint32_t*)&h1;
                pa[2] = *(uint32_t*)&h2; pa[3] = *(uint32_t*)&h3;
                __nv_bfloat162 e0 = __floats2bfloat162_rn(ce[0] - __bfloat162float(h0.x),
                                                          ce[1] - __bfloat162float(h0.y));
                __nv_bfloat162 e1 = __floats2bfloat162_rn(ce[2] - __bfloat162float(h1.x),
                                                          ce[3] - __bfloat162float(h1.y));
                __nv_bfloat162 e2 = __floats2bfloat162_rn(co[0] - __bfloat162float(h2.x),
                                                          co[1] - __bfloat162float(h2.y));
                __nv_bfloat162 e3 = __floats2bfloat162_rn(co[2] - __bfloat162float(h3.x),
                                                          co[3] - __bfloat162float(h3.y));
                pb[0] = *(uint32_t*)&e0; pb[1] = *(uint32_t*)&e1;
                pb[2] = *(uint32_t*)&e2; pb[3] = *(uint32_t*)&e3;
            }
            uint32_t vbase = (uint32_t)(((jks * 16 + (lane & 15)) * FRS
                                         + ((lane >> 4) & 1) * 8) * 2);
            #pragma unroll
            for (int db = 0; db < 4; db++) {
                uint32_t vh[4], vl[4];
                uint32_t vo = vbase + (uint32_t)(db * 32);
                ldmx4t(vh, uVh + vo);
                ldmx4t(vl, uVl + vo);
                mma_bf16(o[db * 2],     pa, vh + 0);
                mma_bf16(o[db * 2 + 1], pa, vh + 2);
                mma_bf16(o[db * 2],     pa, vl + 0);
                mma_bf16(o[db * 2 + 1], pa, vl + 2);
                mma_bf16(o[db * 2],     pb, vh + 0);
                mma_bf16(o[db * 2 + 1], pb, vh + 2);
            }
        }
    }

    float inv0 = 1.0f / l[0], inv1 = 1.0f / l[1];
    int row0 = bm + wid * 16 + (lane >> 2);
    #pragma unroll
    for (int dt = 0; dt < 8; dt++) {
        int col = h * HD + dt * 8 + (lane & 3) * 2;
        float a0 = o[dt][0] * inv0, b0 = o[dt][1] * inv0;
        float a1 = o[dt][2] * inv1, b1 = o[dt][3] * inv1;
        __nv_bfloat162 hh0 = __floats2bfloat162_rn(a0, b0);
        __nv_bfloat162 ll0 = __floats2bfloat162_rn(a0 - __bfloat162float(hh0.x),
                                                   b0 - __bfloat162float(hh0.y));
        __nv_bfloat162 hh1 = __floats2bfloat162_rn(a1, b1);
        __nv_bfloat162 ll1 = __floats2bfloat162_rn(a1 - __bfloat162float(hh1.x),
                                                   b1 - __bfloat162float(hh1.y));
        size_t off0 = (size_t)row0 * HIDDEN + col;
        size_t off1 = (size_t)(row0 + 8) * HIDDEN + col;
        *(uint32_t*)((char*)outh + off0 * 2) = *(uint32_t*)&hh0;
        *(uint32_t*)((char*)outl + off0 * 2) = *(uint32_t*)&ll0;
        *(uint32_t*)((char*)outh + off1 * 2) = *(uint32_t*)&hh1;
        *(uint32_t*)((char*)outl + off1 * 2) = *(uint32_t*)&ll1;
    }
}

// ================= bf16-split GEMM, cp.async, single sync per chunk =================
// BM in {128, 64}; BN=128; 256 threads; 8 warps.
// BM=128: warp tile 64x32 (wm:2 x wn:4). BM=64: warp tile 32x32 (wm:2 x wn:4).
#define RS 40

template <int EPI, int BM>
__global__ void __launch_bounds__(256, 2)
gemm_bf16_kernel(const __nv_bfloat16* __restrict__ Ah, const __nv_bfloat16* __restrict__ Al,
                 const __nv_bfloat16* __restrict__ Bh, const __nv_bfloat16* __restrict__ Bl,
                 float* __restrict__ C, const float* __restrict__ R,
                 __nv_bfloat16* __restrict__ Oh, __nv_bfloat16* __restrict__ Ol,
                 int M, int N, int K) {
    constexpr int MT = (BM == 128) ? 4 : 2;        // m16 tiles per warp
    constexpr int ABY = BM * RS * 2;
    constexpr int BBY = 128 * RS * 2;
    constexpr int STG = 2 * ABY + 2 * BBY;

    extern __shared__ char gsm[];
    int tid = threadIdx.x, lane = tid & 31, wid = tid >> 5;
    int wm = wid >> 2, wn = wid & 3;
    int bm = blockIdx.y * BM, bn = blockIdx.x * 128;

    uint32_t sb = smem_u32(gsm);

    // A loader
    int arow, acpa_n; uint32_t so_a; const char *gAh, *gAl;
    if (BM == 128) {
        arow = tid >> 1; int half = tid & 1; acpa_n = 2;
        so_a = (uint32_t)(arow * 80 + half * 32);
        gAh = (const char*)(Ah + (size_t)(bm + arow) * K + half * 16);
        gAl = (const char*)(Al + (size_t)(bm + arow) * K + half * 16);
    } else {
        arow = tid >> 2; int seg = tid & 3; acpa_n = 1;
        so_a = (uint32_t)(arow * 80 + seg * 16);
        gAh = (const char*)(Ah + (size_t)(bm + arow) * K + seg * 8);
        gAl = (const char*)(Al + (size_t)(bm + arow) * K + seg * 8);
    }
    // B loader (always 128 rows)
    int brow = tid >> 1, bhalf = tid & 1;
    int bgrow = bn + brow;
    bool bok = bgrow < N;
    int browc = bok ? bgrow : (N - 1);
    uint32_t so_b = (uint32_t)(brow * 80 + bhalf * 32);
    const char* gBh = (const char*)(Bh + (size_t)browc * K + bhalf * 16);
    const char* gBl = (const char*)(Bl + (size_t)browc * K + bhalf * 16);
    int bsz = bok ? 16 : 0;

    uint32_t aoff = (uint32_t)(((wm * (MT * 16) + (lane & 15)) * RS + ((lane >> 4) & 1) * 8) * 2);
    uint32_t boff = (uint32_t)(((wn * 32 + ((lane >> 4) & 1) * 8 + (lane & 7)) * RS
                                + ((lane >> 3) & 1) * 8) * 2);

    float acc[MT][4][4] = {};
    int nCh = K >> 5;

    // issue chunk 0
    {
        uint32_t s0 = sb;
        #pragma unroll
        for (int g = 0; g < 2; g++) {
            if (g < acpa_n) {
                cpa16(s0 + so_a + g * 16,       gAh + g * 16, 16);
                cpa16(s0 + ABY + so_a + g * 16, gAl + g * 16, 16);
            }
        }
        cpa16(s0 + 2 * ABY + so_b,            gBh, bsz);
        cpa16(s0 + 2 * ABY + so_b + 16,       gBh + 16, bsz);
        cpa16(s0 + 2 * ABY + BBY + so_b,      gBl, bsz);
        cpa16(s0 + 2 * ABY + BBY + so_b + 16, gBl + 16, bsz);
        cpa_commit();
    }

    for (int s = 0; s < nCh; s++) {
        cpa_wait0();
        __syncthreads();

        if (s + 1 < nCh) {
            uint32_t s1 = sb + (uint32_t)((s + 1) & 1) * STG;
            int kb = (s + 1) * 64;
            #pragma unroll
            for (int g = 0; g < 2; g++) {
                if (g < acpa_n) {
                    cpa16(s1 + so_a + g * 16,       gAh + kb + g * 16, 16);
                    cpa16(s1 + ABY + so_a + g * 16, gAl + kb + g * 16, 16);
                }
            }
            cpa16(s1 + 2 * ABY + so_b,            gBh + kb, bsz);
            cpa16(s1 + 2 * ABY + so_b + 16,       gBh + kb + 16, bsz);
            cpa16(s1 + 2 * ABY + BBY + so_b,      gBl + kb, bsz);
            cpa16(s1 + 2 * ABY + BBY + so_b + 16, gBl + kb + 16, bsz);
            cpa_commit();
        }

        uint32_t st = sb + (uint32_t)(s & 1) * STG;
        uint32_t uAh = st, uAl = st + ABY, uBh = st + 2 * ABY, uBl = st + 2 * ABY + BBY;
        #pragma unroll
        for (int ks = 0; ks < 2; ks++) {
            uint32_t k2 = (uint32_t)(ks * 32);
            uint32_t aH[MT][4], aL[MT][4], bH[2][4], bL[2][4];
            #pragma unroll
            for (int mt = 0; mt < MT; mt++) ldmx4(aH[mt], uAh + aoff + mt * (16 * RS * 2) + k2);
            #pragma unroll
            for (int np = 0; np < 2; np++) ldmx4(bH[np], uBh + boff + np * (16 * RS * 2) + k2);
            #pragma unroll
            for (int mt = 0; mt < MT; mt++)
                #pragma unroll
                for (int nt = 0; nt < 4; nt++)
                    mma_bf16(acc[mt][nt], aH[mt], &bH[nt >> 1][(nt & 1) * 2]);
            #pragma unroll
            for (int np = 0; np < 2; np++) ldmx4(bL[np], uBl + boff + np * (16 * RS * 2) + k2);
            #pragma unroll
            for (int mt = 0; mt < MT; mt++)
                #pragma unroll
                for (int nt = 0; nt < 4; nt++)
                    mma_bf16(acc[mt][nt], aH[mt], &bL[nt >> 1][(nt & 1) * 2]);
            #pragma unroll
            for (int mt = 0; mt < MT; mt++) ldmx4(aL[mt], uAl + aoff + mt * (16 * RS * 2) + k2);
            #pragma unroll
            for (int mt = 0; mt < MT; mt++)
                #pragma unroll
                for (int nt = 0; nt < 4; nt++)
                    mma_bf16(acc[mt][nt], aL[mt], &bH[nt >> 1][(nt & 1) * 2]);
        }
    }

    #pragma unroll
    for (int mt = 0; mt < MT; mt++) {
        int rw = bm + wm * (MT * 16) + mt * 16 + (lane >> 2);
        #pragma unroll
        for (int nt = 0; nt < 4; nt++) {
            int col = bn + wn * 32 + nt * 8 + (lane & 3) * 2;
            if (col < N) {
                float* c = acc[mt][nt];
                float v0 = c[0], v1 = c[1], v2 = c[2], v3 = c[3];
                if (EPI == 1) {
                    float2 r0 = *(const float2*)(R + (size_t)rw * N + col);
                    float2 r1 = *(const float2*)(R + (size_t)(rw + 8) * N + col);
                    v0 += r0.x; v1 += r0.y; v2 += r1.x; v3 += r1.y;
                }
                if (EPI == 2) {
                    v0 = fmaxf(v0, 0.f); v0 *= v0;
                    v1 = fmaxf(v1, 0.f); v1 *= v1;
                    v2 = fmaxf(v2, 0.f); v2 *= v2;
                    v3 = fmaxf(v3, 0.f); v3 *= v3;
                    __nv_bfloat162 hh0 = __floats2bfloat162_rn(v0, v1);
                    __nv_bfloat162 ll0 = __floats2bfloat162_rn(v0 - __bfloat162float(hh0.x),
                                                               v1 - __bfloat162float(hh0.y));
                    __nv_bfloat162 hh1 = __floats2bfloat162_rn(v2, v3);
                    __nv_bfloat162 ll1 = __floats2bfloat162_rn(v2 - __bfloat162float(hh1.x),
                                                               v3 - __bfloat162float(hh1.y));
                    size_t o0 = (size_t)rw * N + col;
                    size_t o1 = (size_t)(rw + 8) * N + col;
                    *(uint32_t*)((char*)Oh + o0 * 2) = *(uint32_t*)&hh0;
                    *(uint32_t*)((char*)Ol + o0 * 2) = *(uint32_t*)&ll0;
                    *(uint32_t*)((char*)Oh + o1 * 2) = *(uint32_t*)&hh1;
                    *(uint32_t*)((char*)Ol + o1 * 2) = *(uint32_t*)&ll1;
                } else {
                    *(float2*)(C + (size_t)rw * N + col) = make_float2(v0, v1);
                    *(float2*)(C + (size_t)(rw + 8) * N + col) = make_float2(v2, v3);
                }
            }
        }
    }
}

#define GSMEM_128 (2 * (2 * 128 * RS * 2 + 2 * 128 * RS * 2))   // 81920
#define GSMEM_64  (2 * (2 * 64 * RS * 2 + 2 * 128 * RS * 2))    // 61440

// ---------------- host launcher ----------------
extern "C" void kernel_launch(void* const* d_in, const int* in_sizes, int n_in,
                              void* d_out, int out_size) {
    const int*   ids  = (const int*)d_in[0];
    const float* wte  = (const float*)d_in[1];
    const float* wqkv = (const float*)d_in[2];
    const float* wo   = (const float*)d_in[3];
    const float* w1   = (const float*)d_in[4];
    const float* w2   = (const float*)d_in[5];
    const float* lm   = (const float*)d_in[6];
    float* out = (float*)d_out;

    float *px, *pqkv, *pcos, *psin;
    __nv_bfloat16 *pwh, *pwl, *psh, *psl, *phh, *phl, *pah, *pal, *pmh, *pml;
    cudaGetSymbolAddress((void**)&px,   g_x);
    cudaGetSymbolAddress((void**)&pqkv, g_qkv);
    cudaGetSymbolAddress((void**)&pcos, g_cos);
    cudaGetSymbolAddress((void**)&psin, g_sin);
    cudaGetSymbolAddress((void**)&pwh,  g_wh);
    cudaGetSymbolAddress((void**)&pwl,  g_wl);
    cudaGetSymbolAddress((void**)&psh,  g_sh);
    cudaGetSymbolAddress((void**)&psl,  g_sl);
    cudaGetSymbolAddress((void**)&phh,  g_hh);
    cudaGetSymbolAddress((void**)&phl,  g_hl);
    cudaGetSymbolAddress((void**)&pah,  g_ah);
    cudaGetSymbolAddress((void**)&pal,  g_al);
    cudaGetSymbolAddress((void**)&pmh,  g_mh);
    cudaGetSymbolAddress((void**)&pml,  g_ml);

    cudaFuncSetAttribute(flash_attn_kernel,
                         cudaFuncAttributeMaxDynamicSharedMemorySize, FLASH_SMEM);
    cudaFuncSetAttribute(gemm_bf16_kernel<0, 128>,
                         cudaFuncAttributeMaxDynamicSharedMemorySize, GSMEM_128);
    cudaFuncSetAttribute(gemm_bf16_kernel<1, 64>,
                         cudaFuncAttributeMaxDynamicSharedMemorySize, GSMEM_64);
    cudaFuncSetAttribute(gemm_bf16_kernel<2, 128>,
                         cudaFuncAttributeMaxDynamicSharedMemorySize, GSMEM_128);

    // ---- weight pre-split ----
    {
        struct { const float* s; size_t off, n; } ws[5] = {
            {wqkv, OFF_WQKV, 25165824ULL},
            {wo,   OFF_WO,    8388608ULL},
            {w1,   OFF_W1,   33554432ULL},
            {w2,   OFF_W2,   33554432ULL},
            {lm,   OFF_LM,   51478528ULL},
        };
        for (int i = 0; i < 5; i++) {
            size_t n4 = ws[i].n / 4;
            wsplit_kernel<<<(unsigned)((n4 + 255) / 256), 256>>>(
                (const float4*)ws[i].s, (uint32_t*)(pwh + ws[i].off),
                (uint32_t*)(pwl + ws[i].off), n4);
        }
    }

    rope_init_kernel<<<SEQ, 32>>>(pcos, psin);
    embed_rmsnorm_kernel<<<SEQ, 256>>>(ids, wte, px);

    for (int l = 0; l < NL; l++) {
        __nv_bfloat16* wqkv_h = pwh + OFF_WQKV + (size_t)l * 3145728;
        __nv_bfloat16* wqkv_l2 = pwl + OFF_WQKV + (size_t)l * 3145728;
        __nv_bfloat16* wo_h = pwh + OFF_WO + (size_t)l * 1048576;
        __nv_bfloat16* wo_l2 = pwl + OFF_WO + (size_t)l * 1048576;
        __nv_bfloat16* w1_h = pwh + OFF_W1 + (size_t)l * 4194304;
        __nv_bfloat16* w1_l2 = pwl + OFF_W1 + (size_t)l * 4194304;
        __nv_bfloat16* w2_h = pwh + OFF_W2 + (size_t)l * 4194304;
        __nv_bfloat16* w2_l2 = pwl + OFF_W2 + (size_t)l * 4194304;

        rmsnorm_split_kernel<<<SEQ, 256>>>(px, phh, phl);
        gemm_bf16_kernel<0, 128><<<dim3(24, 16), 256, GSMEM_128>>>(
            phh, phl, wqkv_h, wqkv_l2, pqkv, nullptr, nullptr, nullptr,
            SEQ, 3 * HIDDEN, HIDDEN);
        qknorm_rope_split_kernel<<<dim3(SEQ, NH, 3), 32>>>(pqkv, pcos, psin, psh, psl);
        flash_attn_kernel<<<dim3(SEQ / 64, NH), 128, FLASH_SMEM>>>(psh, psl, pah, pal);
        gemm_bf16_kernel<1, 64><<<dim3(8, 32), 256, GSMEM_64>>>(
            pah, pal, wo_h, wo_l2, px, px, nullptr, nullptr,
            SEQ, HIDDEN, HIDDEN);

        rmsnorm_split_kernel<<<SEQ, 256>>>(px, phh, phl);
        gemm_bf16_kernel<2, 128><<<dim3(32, 16), 256, GSMEM_128>>>(
            phh, phl, w1_h, w1_l2, nullptr, nullptr, pmh, pml,
            SEQ, FFN, HIDDEN);
        gemm_bf16_kernel<1, 64><<<dim3(8, 32), 256, GSMEM_64>>>(
            pmh, pml, w2_h, w2_l2, px, px, nullptr, nullptr,
            SEQ, HIDDEN, FFN);
    }

    rmsnorm_split_kernel<<<SEQ, 256>>>(px, phh, phl);
    gemm_bf16_kernel<0, 128><<<dim3((VOCABSZ + 127) / 128, 16), 256, GSMEM_128>>>(
        phh, phl, pwh + OFF_LM, pwl + OFF_LM, out, nullptr, nullptr, nullptr,
        SEQ, VOCABSZ, HIDDEN);
}